// round 11
// baseline (speedup 1.0000x reference)
#include <cuda_runtime.h>
#include <cuda_bf16.h>
#include <mma.h>
#include <cstddef>
#include <cstdint>

using namespace nvcuda;

#define BATCH   4
#define TLEN    1024
#define MEMLEN  1024
#define JDIM    2048
#define DMODEL  1024
#define NHEAD   16
#define DHEAD   64
#define KP3     3072      // 3 * DMODEL (compensated K)

// -------- scratch (static __device__ globals; cudaMalloc is forbidden) ------
__device__ __nv_bfloat16 g_x2   [(size_t)BATCH * TLEN * KP3];    // [h|l|h]
__device__ __nv_bfloat16 g_kvin2[(size_t)BATCH * JDIM * KP3];    // [h|l|h]
__device__ __nv_bfloat16 g_a2   [(size_t)BATCH * TLEN * KP3];    // [h|l|h]
__device__ __nv_bfloat16 g_wq2  [(size_t)DMODEL * KP3];          // [h|h|l] (transposed)
__device__ __nv_bfloat16 g_wkv2 [(size_t)2 * DMODEL * KP3];      // [h|h|l]
__device__ __nv_bfloat16 g_wo2  [(size_t)DMODEL * KP3];          // [h|h|l]
__device__ __nv_bfloat16 g_q2   [(size_t)BATCH * NHEAD * TLEN * 128];  // [Qh|Ql]
__device__ __nv_bfloat16 g_rel2 [(size_t)NHEAD * JDIM * 64];           // hi only
__device__ __nv_bfloat16 g_khl  [(size_t)BATCH * NHEAD * JDIM * 128];  // [Kh|Kl]
__device__ __nv_bfloat16 g_vhl  [(size_t)BATCH * NHEAD * JDIM * 128];  // [Vh|Vl]

// ---------------------------------------------------------------------------
__device__ __forceinline__ uint32_t smem_u32(const void* p) {
    uint32_t a;
    asm("{ .reg .u64 t; cvta.to.shared.u64 t, %1; cvt.u32.u64 %0, t; }" : "=r"(a) : "l"(p));
    return a;
}
__device__ __forceinline__ void cpasync16s(uint32_t saddr, const void* gsrc) {
    asm volatile("cp.async.cg.shared.global [%0], [%1], 16;\n" :: "r"(saddr), "l"(gsrc));
}
__device__ __forceinline__ void cpasync16(void* smem_dst, const void* gsrc) {
    cpasync16s((uint32_t)__cvta_generic_to_shared(smem_dst), gsrc);
}
__device__ __forceinline__ void cp_commit() { asm volatile("cp.async.commit_group;\n"); }
__device__ __forceinline__ void cp_wait0()  { asm volatile("cp.async.wait_group 0;\n"); }
__device__ __forceinline__ void cp_wait1()  { asm volatile("cp.async.wait_group 1;\n"); }

__device__ __forceinline__ void split1(float v, __nv_bfloat16& h, __nv_bfloat16& l) {
    h = __float2bfloat16(v);
    l = __float2bfloat16(v - __bfloat162float(h));
}

// raw tensor-core primitives (documented PTX layouts, sm_80+)
__device__ __forceinline__ void ldmx4(uint32_t* r, uint32_t addr) {
    asm volatile("ldmatrix.sync.aligned.m8n8.x4.shared.b16 {%0,%1,%2,%3}, [%4];"
                 : "=r"(r[0]), "=r"(r[1]), "=r"(r[2]), "=r"(r[3]) : "r"(addr));
}
__device__ __forceinline__ void ldmx2t(uint32_t* r, uint32_t addr) {
    asm volatile("ldmatrix.sync.aligned.m8n8.x2.trans.shared.b16 {%0,%1}, [%2];"
                 : "=r"(r[0]), "=r"(r[1]) : "r"(addr));
}
__device__ __forceinline__ void mma16816(float* c, const uint32_t* a, const uint32_t* b) {
    asm volatile("mma.sync.aligned.m16n8k16.row.col.f32.bf16.bf16.f32 "
                 "{%0,%1,%2,%3},{%4,%5,%6,%7},{%8,%9},{%0,%1,%2,%3};"
                 : "+f"(c[0]), "+f"(c[1]), "+f"(c[2]), "+f"(c[3])
                 : "r"(a[0]), "r"(a[1]), "r"(a[2]), "r"(a[3]), "r"(b[0]), "r"(b[1]));
}

// ---------------------------------------------------------------------------
// prep kernels (unchanged)
// ---------------------------------------------------------------------------
__global__ void split3_rows(const float* __restrict__ in, __nv_bfloat16* __restrict__ out,
                            size_t total) {
    size_t i = (size_t)blockIdx.x * blockDim.x + threadIdx.x;
    if (i >= total) return;
    size_t r = i >> 8;
    int c4 = (int)(i & 255) * 4;
    float4 v = *(const float4*)&in[r * DMODEL + c4];
    __nv_bfloat16 h[4], l[4];
    split1(v.x, h[0], l[0]); split1(v.y, h[1], l[1]);
    split1(v.z, h[2], l[2]); split1(v.w, h[3], l[3]);
    __nv_bfloat16* o = out + r * KP3;
    __nv_bfloat162 hp0 = __halves2bfloat162(h[0], h[1]), hp1 = __halves2bfloat162(h[2], h[3]);
    __nv_bfloat162 lp0 = __halves2bfloat162(l[0], l[1]), lp1 = __halves2bfloat162(l[2], l[3]);
    *(__nv_bfloat162*)(o + c4)              = hp0; *(__nv_bfloat162*)(o + c4 + 2)              = hp1;
    *(__nv_bfloat162*)(o + DMODEL + c4)     = lp0; *(__nv_bfloat162*)(o + DMODEL + c4 + 2)     = lp1;
    *(__nv_bfloat162*)(o + 2 * DMODEL + c4) = hp0; *(__nv_bfloat162*)(o + 2 * DMODEL + c4 + 2) = hp1;
}

__global__ void build_kvin_split3(const float* __restrict__ x, const float* __restrict__ mem,
                                  __nv_bfloat16* __restrict__ out) {
    size_t i = (size_t)blockIdx.x * blockDim.x + threadIdx.x;
    const size_t total = (size_t)BATCH * JDIM * 256;
    if (i >= total) return;
    size_t r = i >> 8;
    int c4 = (int)(i & 255) * 4;
    size_t b = r / JDIM, m = r % JDIM;
    float4 v;
    if (m < MEMLEN) v = *(const float4*)&mem[(b * MEMLEN + m) * DMODEL + c4];
    else            v = *(const float4*)&x  [(b * TLEN + (m - MEMLEN)) * DMODEL + c4];
    __nv_bfloat16 h[4], l[4];
    split1(v.x, h[0], l[0]); split1(v.y, h[1], l[1]);
    split1(v.z, h[2], l[2]); split1(v.w, h[3], l[3]);
    __nv_bfloat16* o = out + r * KP3;
    __nv_bfloat162 hp0 = __halves2bfloat162(h[0], h[1]), hp1 = __halves2bfloat162(h[2], h[3]);
    __nv_bfloat162 lp0 = __halves2bfloat162(l[0], l[1]), lp1 = __halves2bfloat162(l[2], l[3]);
    *(__nv_bfloat162*)(o + c4)              = hp0; *(__nv_bfloat162*)(o + c4 + 2)              = hp1;
    *(__nv_bfloat162*)(o + DMODEL + c4)     = lp0; *(__nv_bfloat162*)(o + DMODEL + c4 + 2)     = lp1;
    *(__nv_bfloat162*)(o + 2 * DMODEL + c4) = hp0; *(__nv_bfloat162*)(o + 2 * DMODEL + c4 + 2) = hp1;
}

__global__ void transpose_split3(const float* __restrict__ W, __nv_bfloat16* __restrict__ T2, int N) {
    __shared__ float t[32][33];
    int k0 = blockIdx.y * 32, n0 = blockIdx.x * 32;
    int tx = threadIdx.x, ty = threadIdx.y;
#pragma unroll
    for (int i = 0; i < 32; i += 8)
        t[ty + i][tx] = W[(size_t)(k0 + ty + i) * N + n0 + tx];
    __syncthreads();
#pragma unroll
    for (int i = 0; i < 32; i += 8) {
        float v = t[tx][ty + i];
        int n = n0 + ty + i, k = k0 + tx;
        __nv_bfloat16 h, l;
        split1(v, h, l);
        __nv_bfloat16* o = T2 + (size_t)n * KP3;
        o[k] = h; o[DMODEL + k] = h; o[2 * DMODEL + k] = l;
    }
}

__global__ void build_rel2k(const float* __restrict__ rel, __nv_bfloat16* __restrict__ rel2) {
    size_t i = (size_t)blockIdx.x * blockDim.x + threadIdx.x;
    const size_t total = (size_t)JDIM * NHEAD * 16;
    if (i >= total) return;
    int c4 = (int)(i & 15) * 4;
    int h  = (int)(i >> 4) & 15;
    int u  = (int)(i >> 8);
    float4 v = *(const float4*)&rel[((size_t)u * NHEAD + h) * DHEAD + c4];
    __nv_bfloat16* o = rel2 + ((size_t)h * JDIM + u) * 64;
    *(__nv_bfloat162*)(o + c4)     = __halves2bfloat162(__float2bfloat16(v.x), __float2bfloat16(v.y));
    *(__nv_bfloat162*)(o + c4 + 2) = __halves2bfloat162(__float2bfloat16(v.z), __float2bfloat16(v.w));
}

__global__ void copy_x(const float* __restrict__ x, float* __restrict__ dst) {
    size_t i = (size_t)blockIdx.x * blockDim.x + threadIdx.x;
    const size_t total = (size_t)BATCH * TLEN * DMODEL / 4;
    if (i < total) ((float4*)dst)[i] = ((const float4*)x)[i];
}

// ---------------------------------------------------------------------------
// wmma bf16 GEMM, 128x256 block tile, 8 warps x (64x64), 3-stage cp.async.
// mode 0: C = A@B^T + bias (fp32 out)
// mode 1: q-proj -> q2 [bh][t][128]=[hi|lo]
// mode 2: kv-proj -> khl/vhl [bh][m][128]=[hi|lo]
// ---------------------------------------------------------------------------
#define A_BYTES   10240            // 128 rows x 80 B
#define B_BYTES   20480            // 256 rows x 80 B
#define STG2      (A_BYTES + B_BYTES)   // 30720
#define LDS_ROW   40
#define NSTAGE    3

__global__ __launch_bounds__(256)
void tgemm_wmma(const __nv_bfloat16* __restrict__ A, const __nv_bfloat16* __restrict__ B,
                const float* __restrict__ bias, float* __restrict__ C,
                __nv_bfloat16* __restrict__ q2o,
                __nv_bfloat16* __restrict__ khlo, __nv_bfloat16* __restrict__ vhlo,
                int M, int N, int Kp, int mode) {
    extern __shared__ char sm[];
    const uint32_t sbase = smem_u32(sm);
    float* biasS = (float*)(sm + NSTAGE * STG2);      // [16 x 256]

    const int tid = threadIdx.x;
    const int wid = tid >> 5;
    const int wm = wid >> 2;          // 0..1 -> 64-row half
    const int wn = wid & 3;           // 0..3 -> 64-col quarter
    const int row0 = blockIdx.y * 128;
    const int col0 = blockIdx.x * 256;

    if (mode == 0)
        for (int i = tid; i < 16 * 256; i += 256)
            biasS[i] = bias ? bias[col0 + (i & 255)] : 0.f;

    auto loadStage = [&](int s, int k0) {
        uint32_t ab = sbase + s * STG2;
        uint32_t bb = ab + A_BYTES;
#pragma unroll
        for (int p = 0; p < 2; ++p) {
            int i = tid + p * 256;
            int r = i >> 2, qq = i & 3;
            cpasync16s(ab + r * 80 + qq * 16,
                       (const char*)A + (((size_t)(row0 + r)) * Kp + k0 + qq * 8) * 2);
        }
#pragma unroll
        for (int p = 0; p < 4; ++p) {
            int i = tid + p * 256;
            int r = i >> 2, qq = i & 3;
            cpasync16s(bb + r * 80 + qq * 16,
                       (const char*)B + (((size_t)(col0 + r)) * Kp + k0 + qq * 8) * 2);
        }
    };

    wmma::fragment<wmma::accumulator, 16, 16, 16, float> acc[4][4];
    __syncthreads();
    if (mode == 0) {
#pragma unroll
        for (int i = 0; i < 4; ++i)
#pragma unroll
            for (int j = 0; j < 4; ++j)
                wmma::load_matrix_sync(acc[i][j], &biasS[wn * 64 + j * 16], 256, wmma::mem_row_major);
    } else {
#pragma unroll
        for (int i = 0; i < 4; ++i)
#pragma unroll
            for (int j = 0; j < 4; ++j)
                wmma::fill_fragment(acc[i][j], 0.f);
    }

    loadStage(0, 0); cp_commit();
    loadStage(1, 32); cp_commit();

    const int nst = Kp / 32;
    for (int st = 0; st < nst; ++st) {
        if (st == nst - 1) cp_wait0(); else cp_wait1();
        __syncthreads();
        if (st + 2 < nst) { loadStage((st + 2) % NSTAGE, (st + 2) * 32); cp_commit(); }

        const __nv_bfloat16* as = (const __nv_bfloat16*)(sm + (st % NSTAGE) * STG2);
        const __nv_bfloat16* bs = as + A_BYTES / 2;

#pragma unroll
        for (int kk = 0; kk < 2; ++kk) {
            wmma::fragment<wmma::matrix_a, 16, 16, 16, __nv_bfloat16, wmma::row_major> af[4];
            wmma::fragment<wmma::matrix_b, 16, 16, 16, __nv_bfloat16, wmma::col_major> bfr[4];
#pragma unroll
            for (int i = 0; i < 4; ++i)
                wmma::load_matrix_sync(af[i], as + (wm * 64 + i * 16) * LDS_ROW + kk * 16, LDS_ROW);
#pragma unroll
            for (int j = 0; j < 4; ++j)
                wmma::load_matrix_sync(bfr[j], bs + (wn * 64 + j * 16) * LDS_ROW + kk * 16, LDS_ROW);
#pragma unroll
            for (int i = 0; i < 4; ++i)
#pragma unroll
                for (int j = 0; j < 4; ++j)
                    wmma::mma_sync(acc[i][j], af[i], bfr[j], acc[i][j]);
        }
    }

    if (mode == 0) {
#pragma unroll
        for (int i = 0; i < 4; ++i)
#pragma unroll
            for (int j = 0; j < 4; ++j)
                wmma::store_matrix_sync(&C[(size_t)(row0 + wm * 64 + i * 16) * N + col0 + wn * 64 + j * 16],
                                        acc[i][j], N, wmma::mem_row_major);
        return;
    }

    // modes 1/2: stage fragments to smem fp32 tile [128][264], split+scatter
    __syncthreads();
    float* Cs = (float*)sm;
#pragma unroll
    for (int i = 0; i < 4; ++i)
#pragma unroll
        for (int j = 0; j < 4; ++j)
            wmma::store_matrix_sync(&Cs[(size_t)(wm * 64 + i * 16) * 264 + wn * 64 + j * 16],
                                    acc[i][j], 264, wmma::mem_row_major);
    __syncthreads();

    if (mode == 1) {
        for (int idx = tid; idx < 128 * 256; idx += 256) {
            int r = idx >> 8, c = idx & 255;
            float v = Cs[r * 264 + c];
            __nv_bfloat16 hv, lv; split1(v, hv, lv);
            int bt = row0 + r, gc = col0 + c;
            int b = bt >> 10, t = bt & 1023;
            int h = gc >> 6, cc = gc & 63;
            __nv_bfloat16* o = q2o + (((size_t)(b * NHEAD + h) * TLEN + t)) * 128 + cc;
            o[0] = hv; o[64] = lv;
        }
    } else {
        for (int idx = tid; idx < 128 * 256; idx += 256) {
            int r = idx >> 8, c = idx & 255;
            float v = Cs[r * 264 + c];
            __nv_bfloat16 hv, lv; split1(v, hv, lv);
            int rg = row0 + r, gc = col0 + c;
            int b = rg >> 11, m = rg & 2047;
            __nv_bfloat16* dst = (gc < DMODEL) ? khlo : vhlo;
            int gcl = (gc < DMODEL) ? gc : gc - DMODEL;
            int h = gcl >> 6, cc = gcl & 63;
            __nv_bfloat16* o = dst + (((size_t)(b * NHEAD + h) * JDIM + m)) * 128 + cc;
            o[0] = hv; o[64] = lv;
        }
    }
}

// ---------------------------------------------------------------------------
// wmma flash attention (unchanged from round 10)
// ---------------------------------------------------------------------------
struct __align__(16) AttnW {
    __nv_bfloat16 Q2s[64][136];       // [Qh(64) | Ql(64)]
    __nv_bfloat16 Khl[2][64][136];    // [Kh | Kl] double-buffered
    __nv_bfloat16 Vhl[2][64][136];    // [Vh | Vl] double-buffered
    __nv_bfloat16 Wh[2][64][72];      // W span ring (hi only)
    float         Sx[64][72];         // QK scores
    float         Rx[2][64][68];      // rel scores ring (64-col halves)
    __nv_bfloat16 Phl[64][136];       // [Ph | Pl]
    float m_s[64];
    float l_s[64];
    float alpha_s[64];
};

__device__ __forceinline__ void aw_pf_K(AttnW& S, int bb, const __nv_bfloat16* __restrict__ khl,
                                        size_t bh, int m0, int tid) {
#pragma unroll
    for (int p = 0; p < 4; ++p) {
        int i = tid + p * 256;
        int r = i >> 4, c = i & 15;
        cpasync16(&S.Khl[bb][r][c * 8], khl + (bh * JDIM + (size_t)(m0 + r)) * 128 + c * 8);
    }
}
__device__ __forceinline__ void aw_pf_V(AttnW& S, int bb, const __nv_bfloat16* __restrict__ vhl,
                                        size_t bh, int m0, int tid) {
#pragma unroll
    for (int p = 0; p < 4; ++p) {
        int i = tid + p * 256;
        int r = i >> 4, c = i & 15;
        cpasync16(&S.Vhl[bb][r][c * 8], vhl + (bh * JDIM + (size_t)(m0 + r)) * 128 + c * 8);
    }
}
__device__ __forceinline__ void aw_pf_W(AttnW& S, int slot, const __nv_bfloat16* __restrict__ rel2,
                                        int h, int ubase, int tid) {
#pragma unroll
    for (int p = 0; p < 2; ++p) {
        int i = tid + p * 256;
        int o = i >> 3, c = i & 7;
        int u = ubase + o; if (u > JDIM - 1) u = JDIM - 1;
        cpasync16(&S.Wh[slot][o][c * 8], rel2 + ((size_t)h * JDIM + u) * 64 + c * 8);
    }
}

__global__ __launch_bounds__(256, 1)
void attn_wmma(const __nv_bfloat16* __restrict__ q2,
               const __nv_bfloat16* __restrict__ khl,
               const __nv_bfloat16* __restrict__ vhl,
               const __nv_bfloat16* __restrict__ rel2,
               __nv_bfloat16* __restrict__ a2) {
    extern __shared__ char smem_raw[];
    AttnW& S = *reinterpret_cast<AttnW*>(smem_raw);

    const int b  = blockIdx.z;
    const int h  = blockIdx.y;
    const int rb = (int)gridDim.x - 1 - (int)blockIdx.x;   // long blocks first
    const int r0 = rb * 64;
    const size_t bh = (size_t)(b * NHEAD + h);
    const int tid = threadIdx.x;
    const int wid = tid >> 5;
    const int lane = tid & 31;
    const int wm = wid >> 2;     // 0..1
    const int wn = wid & 3;      // 0..3
    const int sy = tid >> 4;     // 0..15
    const int sx = tid & 15;     // 0..15
    const int wm2 = wid & 3;     // PV row tile (16 rows)
    const int wn2 = wid >> 2;    // PV col half (32 cols)
    const int g   = lane >> 2;
    const int tig = lane & 3;

#pragma unroll
    for (int p = 0; p < 4; ++p) {
        int i = tid + p * 256;
        int r = i >> 4, c = i & 15;
        cpasync16(&S.Q2s[r][c * 8],
                  q2 + (bh * TLEN + (size_t)(r0 + r)) * 128 + c * 8);
    }
    aw_pf_K(S, 0, khl, bh, 0, tid);
    aw_pf_V(S, 0, vhl, bh, 0, tid);
    aw_pf_W(S, 1, rel2, h, 960 - r0, tid);
    aw_pf_W(S, 0, rel2, h, 1024 - r0, tid);
    cp_commit();

    if (tid < 64) { S.m_s[tid] = -1e30f; S.l_s[tid] = 0.f; }

    float accf[4][4];
#pragma unroll
    for (int i = 0; i < 4; ++i)
#pragma unroll
        for (int j = 0; j < 4; ++j) accf[i][j] = 0.f;

    const int ntiles = min(32, rb + 17);

    for (int mt = 0; mt < ntiles; ++mt) {
        const int cur = mt & 1;
        const int prv = cur ^ 1;
        const int m0  = mt * 64;

        cp_wait0();
        __syncthreads();

        if (mt + 1 < ntiles) {
            aw_pf_K(S, prv, khl, bh, m0 + 64, tid);
            aw_pf_V(S, prv, vhl, bh, m0 + 64, tid);
            cp_commit();
        }

        // ---- S: 3 compensated wmma passes (64x64) ----
        {
            wmma::fragment<wmma::accumulator, 16, 16, 16, float> sacc[2];
#pragma unroll
            for (int i = 0; i < 2; ++i) wmma::fill_fragment(sacc[i], 0.f);
#pragma unroll
            for (int pass = 0; pass < 3; ++pass) {
                const int aoff = (pass == 1) ? 64 : 0;
                const int boff = (pass == 2) ? 64 : 0;
#pragma unroll
                for (int k16 = 0; k16 < 4; ++k16) {
                    wmma::fragment<wmma::matrix_a, 16, 16, 16, __nv_bfloat16, wmma::row_major> af[2];
                    wmma::fragment<wmma::matrix_b, 16, 16, 16, __nv_bfloat16, wmma::col_major> bfr;
#pragma unroll
                    for (int i = 0; i < 2; ++i)
                        wmma::load_matrix_sync(af[i], &S.Q2s[wm * 32 + i * 16][aoff + k16 * 16], 136);
                    wmma::load_matrix_sync(bfr, &S.Khl[cur][wn * 16][boff + k16 * 16], 136);
#pragma unroll
                    for (int i = 0; i < 2; ++i)
                        wmma::mma_sync(sacc[i], af[i], bfr, sacc[i]);
                }
            }
#pragma unroll
            for (int i = 0; i < 2; ++i)
                wmma::store_matrix_sync(&S.Sx[wm * 32 + i * 16][wn * 16], sacc[i], 72,
                                        wmma::mem_row_major);
        }
        // ---- R: new 64x64 half; at mt==0 also the left half ----
        {
            const int nR = (mt == 0) ? 2 : 1;
            for (int rr = 0; rr < nR; ++rr) {
                const int slot = (rr == 0) ? cur : prv;
                wmma::fragment<wmma::accumulator, 16, 16, 16, float> racc[2];
#pragma unroll
                for (int i = 0; i < 2; ++i) wmma::fill_fragment(racc[i], 0.f);
#pragma unroll
                for (int k16 = 0; k16 < 4; ++k16) {
                    wmma::fragment<wmma::matrix_a, 16, 16, 16, __nv_bfloat16, wmma::row_major> af[2];
                    wmma::fragment<wmma::matrix_b, 16, 16, 16, __nv_bfloat16, wmma::col_major> bfr;
#pragma unroll
                    for (int i = 0; i < 2; ++i)
                        wmma::load_matrix_sync(af[i], &S.Q2s[wm * 32 + i * 16][k16 * 16], 136);
                    wmma::load_matrix_sync(bfr, &S.Wh[slot][wn * 16][k16 * 16], 72);
#pragma unroll
                    for (int i = 0; i < 2; ++i)
                        wmma::mma_sync(racc[i], af[i], bfr, racc[i]);
                }
#pragma unroll
                for (int i = 0; i < 2; ++i)
                    wmma::store_matrix_sync(&S.Rx[slot][wm * 32 + i * 16][wn * 16], racc[i], 68,
                                            wmma::mem_row_major);
            }
        }
        __syncthreads();

        if (mt + 1 < ntiles) {
            aw_pf_W(S, (mt + 1) & 1, rel2, h, m0 + 1088 - r0, tid);
            cp_commit();
        }

        // ---- softmax (SIMT), P -> bf16 hi/lo ----
#pragma unroll
        for (int i = 0; i < 4; ++i) {
            const int rl = 4 * sy + i;
            const int mlim = r0 + rl + MEMLEN - m0;
            const int ro = 63 - rl;
            float4 sv = *(const float4*)&S.Sx[rl][4 * sx];
            float sraw[4] = {sv.x, sv.y, sv.z, sv.w};
            float sc[4];
#pragma unroll
            for (int j = 0; j < 4; ++j) {
                int o = 4 * sx + j + ro;
                float rv = (o < 64) ? S.Rx[prv][rl][o] : S.Rx[cur][rl][o - 64];
                sc[j] = (sraw[j] + rv) * 0.125f;
                if (4 * sx + j > mlim) sc[j] = -1e30f;
            }
            float rmax = fmaxf(fmaxf(sc[0], sc[1]), fmaxf(sc[2], sc[3]));
            rmax = fmaxf(rmax, __shfl_xor_sync(0xffffffffu, rmax, 1));
            rmax = fmaxf(rmax, __shfl_xor_sync(0xffffffffu, rmax, 2));
            rmax = fmaxf(rmax, __shfl_xor_sync(0xffffffffu, rmax, 4));
            rmax = fmaxf(rmax, __shfl_xor_sync(0xffffffffu, rmax, 8));
            float mold = S.m_s[rl];
            float mnew = fmaxf(mold, rmax);
            float alpha = __expf(mold - mnew);
            float lsum = 0.f;
            __nv_bfloat16 ph[4], pl[4];
#pragma unroll
            for (int j = 0; j < 4; ++j) {
                float p = __expf(sc[j] - mnew);
                lsum += p;
                ph[j] = __float2bfloat16(p);
                pl[j] = __float2bfloat16(p - __bfloat162float(ph[j]));
            }
            lsum += __shfl_xor_sync(0xffffffffu, lsum, 1);
            lsum += __shfl_xor_sync(0xffffffffu, lsum, 2);
            lsum += __shfl_xor_sync(0xffffffffu, lsum, 4);
            lsum += __shfl_xor_sync(0xffffffffu, lsum, 8);
            if (sx == 0) {
                S.m_s[rl] = mnew;
                S.l_s[rl] = S.l_s[rl] * alpha + lsum;
                S.alpha_s[rl] = alpha;
            }
            *(__nv_bfloat162*)&S.Phl[rl][4 * sx]          = __halves2bfloat162(ph[0], ph[1]);
            *(__nv_bfloat162*)&S.Phl[rl][4 * sx + 2]      = __halves2bfloat162(ph[2], ph[3]);
            *(__nv_bfloat162*)&S.Phl[rl][64 + 4 * sx]     = __halves2bfloat162(pl[0], pl[1]);
            *(__nv_bfloat162*)&S.Phl[rl][64 + 4 * sx + 2] = __halves2bfloat162(pl[2], pl[3]);
        }
        __syncthreads();

        // ---- PV: raw mma.sync, register accumulators ----
        {
            const int rowbase = wm2 * 16;
            const int colbase = wn2 * 32;
            float al1 = S.alpha_s[rowbase + g];
            float al2 = S.alpha_s[rowbase + 8 + g];
#pragma unroll
            for (int nt = 0; nt < 4; ++nt) {
                accf[nt][0] *= al1; accf[nt][1] *= al1;
                accf[nt][2] *= al2; accf[nt][3] *= al2;
            }
            uint32_t aPh[4][4], aPl[4][4];
            {
                int s = lane >> 3, rr2 = lane & 7;
                int arow = rowbase + (s & 1) * 8 + rr2;
                int acol = (s >> 1) * 8;
#pragma unroll
                for (int k16 = 0; k16 < 4; ++k16) {
                    ldmx4(aPh[k16], smem_u32(&S.Phl[arow][acol + k16 * 16]));
                    ldmx4(aPl[k16], smem_u32(&S.Phl[arow][64 + acol + k16 * 16]));
                }
            }
            {
                int s = (lane >> 3) & 1, rr2 = lane & 7;
#pragma unroll
                for (int k16 = 0; k16 < 4; ++k16) {
                    int vrow = k16 * 16 + s * 8 + rr2;
#pragma unroll
                    for (int nt = 0; nt < 4; ++nt) {
                        uint32_t bhv[2], blv[2];
                        ldmx2t(bhv, smem_u32(&S.Vhl[cur][vrow][colbase + nt * 8]));
                        ldmx2t(blv, smem_u32(&S.Vhl[cur][vrow][64 + colbase + nt * 8]));
                        mma16816(accf[nt], aPh[k16], bhv);
                        mma16816(accf[nt], aPl[k16], bhv);
                        mma16816(accf[nt], aPh[k16], blv);
                    }
                }
            }
        }
    }

    __syncthreads();
    // epilogue from fragments: write a2 [row][3072] = [h | l | h]
    {
        const int rowbase = wm2 * 16;
        const int colbase = wn2 * 32;
        int r1 = rowbase + g, r2 = r1 + 8;
        float inv1 = 1.f / S.l_s[r1];
        float inv2 = 1.f / S.l_s[r2];
        size_t grow1 = (size_t)(b * TLEN + r0 + r1) * KP3;
        size_t grow2 = (size_t)(b * TLEN + r0 + r2) * KP3;
#pragma unroll
        for (int nt = 0; nt < 4; ++nt) {
            int col = h * 64 + colbase + nt * 8 + 2 * tig;
            float v0 = accf[nt][0] * inv1, v1 = accf[nt][1] * inv1;
            float v2 = accf[nt][2] * inv2, v3 = accf[nt][3] * inv2;
            __nv_bfloat16 h0, l0, h1, l1, h2, l2, h3, l3;
            split1(v0, h0, l0); split1(v1, h1, l1);
            split1(v2, h2, l2); split1(v3, h3, l3);
            __nv_bfloat16* o1 = a2 + grow1 + col;
            __nv_bfloat16* o2 = a2 + grow2 + col;
            *(__nv_bfloat162*)(o1)              = __halves2bfloat162(h0, h1);
            *(__nv_bfloat162*)(o1 + DMODEL)     = __halves2bfloat162(l0, l1);
            *(__nv_bfloat162*)(o1 + 2 * DMODEL) = __halves2bfloat162(h0, h1);
            *(__nv_bfloat162*)(o2)              = __halves2bfloat162(h2, h3);
            *(__nv_bfloat162*)(o2 + DMODEL)     = __halves2bfloat162(l2, l3);
            *(__nv_bfloat162*)(o2 + 2 * DMODEL) = __halves2bfloat162(h2, h3);
        }
    }
}

// ---------------------------------------------------------------------------
extern "C" void kernel_launch(void* const* d_in, const int* in_sizes, int n_in,
                              void* d_out, int out_size) {
    const float* x    = (const float*)d_in[0];
    const float* mem  = (const float*)d_in[1];
    const float* wq   = (const float*)d_in[2];
    const float* wkv  = (const float*)d_in[3];
    const float* wo   = (const float*)d_in[4];
    const float* bo   = (const float*)d_in[5];
    const float* relw = (const float*)d_in[6];

    float* out_main = (float*)d_out;
    float* mem_next = out_main + (size_t)BATCH * TLEN * DMODEL;

    __nv_bfloat16 *x2, *kvin2, *a2, *wq2, *wkv2, *wo2, *q2, *rel2, *khl, *vhl;
    cudaGetSymbolAddress((void**)&x2,    g_x2);
    cudaGetSymbolAddress((void**)&kvin2, g_kvin2);
    cudaGetSymbolAddress((void**)&a2,    g_a2);
    cudaGetSymbolAddress((void**)&wq2,   g_wq2);
    cudaGetSymbolAddress((void**)&wkv2,  g_wkv2);
    cudaGetSymbolAddress((void**)&wo2,   g_wo2);
    cudaGetSymbolAddress((void**)&q2,    g_q2);
    cudaGetSymbolAddress((void**)&rel2,  g_rel2);
    cudaGetSymbolAddress((void**)&khl,   g_khl);
    cudaGetSymbolAddress((void**)&vhl,   g_vhl);

    // pipeline needs 3*30720 + 16KB bias = 108544; epilogue scratch 128*264*4 = 135168
    const int TG_SMEM = 135168;
    const int AW_SMEM = (int)sizeof(AttnW);
    cudaFuncSetAttribute(tgemm_wmma, cudaFuncAttributeMaxDynamicSharedMemorySize, TG_SMEM);
    cudaFuncSetAttribute(attn_wmma,  cudaFuncAttributeMaxDynamicSharedMemorySize, AW_SMEM);

    // operand prep
    {
        size_t tot = (size_t)BATCH * TLEN * 256;
        split3_rows<<<(unsigned)((tot + 255) / 256), 256>>>(x, x2, tot);
    }
    {
        size_t tot = (size_t)BATCH * JDIM * 256;
        build_kvin_split3<<<(unsigned)((tot + 255) / 256), 256>>>(x, mem, kvin2);
    }
    transpose_split3<<<dim3(DMODEL / 32, DMODEL / 32), dim3(32, 8)>>>(wq, wq2, DMODEL);
    transpose_split3<<<dim3(2 * DMODEL / 32, DMODEL / 32), dim3(32, 8)>>>(wkv, wkv2, 2 * DMODEL);
    transpose_split3<<<dim3(DMODEL / 32, DMODEL / 32), dim3(32, 8)>>>(wo, wo2, DMODEL);
    {
        size_t tot = (size_t)JDIM * NHEAD * 16;
        build_rel2k<<<(unsigned)((tot + 255) / 256), 256>>>(relw, rel2);
    }

    // q-proj -> q2 (mode 1); 128x256 tiles
    tgemm_wmma<<<dim3(DMODEL / 256, BATCH * TLEN / 128), 256, TG_SMEM>>>(
        x2, wq2, nullptr, nullptr, q2, nullptr, nullptr, BATCH * TLEN, DMODEL, KP3, 1);
    // kv-proj -> khl/vhl (mode 2)
    tgemm_wmma<<<dim3(2 * DMODEL / 256, BATCH * JDIM / 128), 256, TG_SMEM>>>(
        kvin2, wkv2, nullptr, nullptr, nullptr, khl, vhl, BATCH * JDIM, 2 * DMODEL, KP3, 2);
    // flash attention -> a2
    attn_wmma<<<dim3(TLEN / 64, NHEAD, BATCH), 256, AW_SMEM>>>(q2, khl, vhl, rel2, a2);
    // out = attn @ wo + bo (mode 0)
    tgemm_wmma<<<dim3(DMODEL / 256, BATCH * TLEN / 128), 256, TG_SMEM>>>(
        a2, wo2, bo, out_main, nullptr, nullptr, nullptr, BATCH * TLEN, DMODEL, KP3, 0);
    // mem_next = x
    {
        size_t n4 = (size_t)BATCH * TLEN * DMODEL / 4;
        copy_x<<<(unsigned)((n4 + 255) / 256), 256>>>(x, mem_next);
    }
}

// round 14
// speedup vs baseline: 1.2174x; 1.2174x over previous
#include <cuda_runtime.h>
#include <cuda_bf16.h>
#include <mma.h>
#include <cstddef>
#include <cstdint>

using namespace nvcuda;

#define BATCH   4
#define TLEN    1024
#define MEMLEN  1024
#define JDIM    2048
#define DMODEL  1024
#define NHEAD   16
#define DHEAD   64
#define KP3     3072      // 3 * DMODEL (compensated K)

// -------- scratch (static __device__ globals; cudaMalloc is forbidden) ------
__device__ __nv_bfloat16 g_x2   [(size_t)BATCH * TLEN * KP3];    // [h|l|h]
__device__ __nv_bfloat16 g_kvin2[(size_t)BATCH * JDIM * KP3];    // [h|l|h]
__device__ __nv_bfloat16 g_a2   [(size_t)BATCH * TLEN * KP3];    // [h|l|h]
__device__ __nv_bfloat16 g_wq2  [(size_t)DMODEL * KP3];          // [h|h|l] (transposed)
__device__ __nv_bfloat16 g_wkv2 [(size_t)2 * DMODEL * KP3];      // [h|h|l]
__device__ __nv_bfloat16 g_wo2  [(size_t)DMODEL * KP3];          // [h|h|l]
__device__ __nv_bfloat16 g_q2   [(size_t)BATCH * NHEAD * TLEN * 128];  // [Qh|Ql]
__device__ __nv_bfloat16 g_rel2 [(size_t)NHEAD * JDIM * 64];           // hi only
__device__ __nv_bfloat16 g_khl  [(size_t)BATCH * NHEAD * JDIM * 128];  // [Kh|Kl]
__device__ __nv_bfloat16 g_vhl  [(size_t)BATCH * NHEAD * JDIM * 128];  // [Vh|Vl]

// ---------------------------------------------------------------------------
__device__ __forceinline__ uint32_t smem_u32(const void* p) {
    uint32_t a;
    asm("{ .reg .u64 t; cvta.to.shared.u64 t, %1; cvt.u32.u64 %0, t; }" : "=r"(a) : "l"(p));
    return a;
}
__device__ __forceinline__ void cpasync16s(uint32_t saddr, const void* gsrc) {
    asm volatile("cp.async.cg.shared.global [%0], [%1], 16;\n" :: "r"(saddr), "l"(gsrc));
}
__device__ __forceinline__ void cpasync16(void* smem_dst, const void* gsrc) {
    cpasync16s((uint32_t)__cvta_generic_to_shared(smem_dst), gsrc);
}
__device__ __forceinline__ void cp_commit() { asm volatile("cp.async.commit_group;\n"); }
__device__ __forceinline__ void cp_wait0()  { asm volatile("cp.async.wait_group 0;\n"); }
__device__ __forceinline__ void cp_wait1()  { asm volatile("cp.async.wait_group 1;\n"); }

__device__ __forceinline__ void split1(float v, __nv_bfloat16& h, __nv_bfloat16& l) {
    h = __float2bfloat16(v);
    l = __float2bfloat16(v - __bfloat162float(h));
}
// pack two bf16 into a uint32 (lo in low half)
__device__ __forceinline__ uint32_t packbf2(__nv_bfloat16 lo, __nv_bfloat16 hi) {
    return (uint32_t)__bfloat16_as_ushort(lo) | ((uint32_t)__bfloat16_as_ushort(hi) << 16);
}

// raw tensor-core primitives (documented PTX layouts, sm_80+)
__device__ __forceinline__ void ldmx4(uint32_t* r, uint32_t addr) {
    asm volatile("ldmatrix.sync.aligned.m8n8.x4.shared.b16 {%0,%1,%2,%3}, [%4];"
                 : "=r"(r[0]), "=r"(r[1]), "=r"(r[2]), "=r"(r[3]) : "r"(addr));
}
__device__ __forceinline__ void ldmx2(uint32_t* r, uint32_t addr) {
    asm volatile("ldmatrix.sync.aligned.m8n8.x2.shared.b16 {%0,%1}, [%2];"
                 : "=r"(r[0]), "=r"(r[1]) : "r"(addr));
}
__device__ __forceinline__ void ldmx2t(uint32_t* r, uint32_t addr) {
    asm volatile("ldmatrix.sync.aligned.m8n8.x2.trans.shared.b16 {%0,%1}, [%2];"
                 : "=r"(r[0]), "=r"(r[1]) : "r"(addr));
}
__device__ __forceinline__ void mma16816(float* c, const uint32_t* a, const uint32_t* b) {
    asm volatile("mma.sync.aligned.m16n8k16.row.col.f32.bf16.bf16.f32 "
                 "{%0,%1,%2,%3},{%4,%5,%6,%7},{%8,%9},{%0,%1,%2,%3};"
                 : "+f"(c[0]), "+f"(c[1]), "+f"(c[2]), "+f"(c[3])
                 : "r"(a[0]), "r"(a[1]), "r"(a[2]), "r"(a[3]), "r"(b[0]), "r"(b[1]));
}

// ---------------------------------------------------------------------------
// prep kernels (unchanged)
// ---------------------------------------------------------------------------
__global__ void split3_rows(const float* __restrict__ in, __nv_bfloat16* __restrict__ out,
                            size_t total) {
    size_t i = (size_t)blockIdx.x * blockDim.x + threadIdx.x;
    if (i >= total) return;
    size_t r = i >> 8;
    int c4 = (int)(i & 255) * 4;
    float4 v = *(const float4*)&in[r * DMODEL + c4];
    __nv_bfloat16 h[4], l[4];
    split1(v.x, h[0], l[0]); split1(v.y, h[1], l[1]);
    split1(v.z, h[2], l[2]); split1(v.w, h[3], l[3]);
    __nv_bfloat16* o = out + r * KP3;
    __nv_bfloat162 hp0 = __halves2bfloat162(h[0], h[1]), hp1 = __halves2bfloat162(h[2], h[3]);
    __nv_bfloat162 lp0 = __halves2bfloat162(l[0], l[1]), lp1 = __halves2bfloat162(l[2], l[3]);
    *(__nv_bfloat162*)(o + c4)              = hp0; *(__nv_bfloat162*)(o + c4 + 2)              = hp1;
    *(__nv_bfloat162*)(o + DMODEL + c4)     = lp0; *(__nv_bfloat162*)(o + DMODEL + c4 + 2)     = lp1;
    *(__nv_bfloat162*)(o + 2 * DMODEL + c4) = hp0; *(__nv_bfloat162*)(o + 2 * DMODEL + c4 + 2) = hp1;
}

__global__ void build_kvin_split3(const float* __restrict__ x, const float* __restrict__ mem,
                                  __nv_bfloat16* __restrict__ out) {
    size_t i = (size_t)blockIdx.x * blockDim.x + threadIdx.x;
    const size_t total = (size_t)BATCH * JDIM * 256;
    if (i >= total) return;
    size_t r = i >> 8;
    int c4 = (int)(i & 255) * 4;
    size_t b = r / JDIM, m = r % JDIM;
    float4 v;
    if (m < MEMLEN) v = *(const float4*)&mem[(b * MEMLEN + m) * DMODEL + c4];
    else            v = *(const float4*)&x  [(b * TLEN + (m - MEMLEN)) * DMODEL + c4];
    __nv_bfloat16 h[4], l[4];
    split1(v.x, h[0], l[0]); split1(v.y, h[1], l[1]);
    split1(v.z, h[2], l[2]); split1(v.w, h[3], l[3]);
    __nv_bfloat16* o = out + r * KP3;
    __nv_bfloat162 hp0 = __halves2bfloat162(h[0], h[1]), hp1 = __halves2bfloat162(h[2], h[3]);
    __nv_bfloat162 lp0 = __halves2bfloat162(l[0], l[1]), lp1 = __halves2bfloat162(l[2], l[3]);
    *(__nv_bfloat162*)(o + c4)              = hp0; *(__nv_bfloat162*)(o + c4 + 2)              = hp1;
    *(__nv_bfloat162*)(o + DMODEL + c4)     = lp0; *(__nv_bfloat162*)(o + DMODEL + c4 + 2)     = lp1;
    *(__nv_bfloat162*)(o + 2 * DMODEL + c4) = hp0; *(__nv_bfloat162*)(o + 2 * DMODEL + c4 + 2) = hp1;
}

__global__ void transpose_split3(const float* __restrict__ W, __nv_bfloat16* __restrict__ T2, int N) {
    __shared__ float t[32][33];
    int k0 = blockIdx.y * 32, n0 = blockIdx.x * 32;
    int tx = threadIdx.x, ty = threadIdx.y;
#pragma unroll
    for (int i = 0; i < 32; i += 8)
        t[ty + i][tx] = W[(size_t)(k0 + ty + i) * N + n0 + tx];
    __syncthreads();
#pragma unroll
    for (int i = 0; i < 32; i += 8) {
        float v = t[tx][ty + i];
        int n = n0 + ty + i, k = k0 + tx;
        __nv_bfloat16 h, l;
        split1(v, h, l);
        __nv_bfloat16* o = T2 + (size_t)n * KP3;
        o[k] = h; o[DMODEL + k] = h; o[2 * DMODEL + k] = l;
    }
}

__global__ void build_rel2k(const float* __restrict__ rel, __nv_bfloat16* __restrict__ rel2) {
    size_t i = (size_t)blockIdx.x * blockDim.x + threadIdx.x;
    const size_t total = (size_t)JDIM * NHEAD * 16;
    if (i >= total) return;
    int c4 = (int)(i & 15) * 4;
    int h  = (int)(i >> 4) & 15;
    int u  = (int)(i >> 8);
    float4 v = *(const float4*)&rel[((size_t)u * NHEAD + h) * DHEAD + c4];
    __nv_bfloat16* o = rel2 + ((size_t)h * JDIM + u) * 64;
    *(__nv_bfloat162*)(o + c4)     = __halves2bfloat162(__float2bfloat16(v.x), __float2bfloat16(v.y));
    *(__nv_bfloat162*)(o + c4 + 2) = __halves2bfloat162(__float2bfloat16(v.z), __float2bfloat16(v.w));
}

__global__ void copy_x(const float* __restrict__ x, float* __restrict__ dst) {
    size_t i = (size_t)blockIdx.x * blockDim.x + threadIdx.x;
    const size_t total = (size_t)BATCH * TLEN * DMODEL / 4;
    if (i < total) ((float4*)dst)[i] = ((const float4*)x)[i];
}

// ---------------------------------------------------------------------------
// wmma bf16 GEMM, 128x128 tile (round-10 config), 3-stage cp.async.
// mode 0: C = A@B^T + bias ; mode 1: q-proj -> q2 ; mode 2: kv-proj -> khl/vhl
// ---------------------------------------------------------------------------
#define STG_BYTES 20480
#define LDS_ROW   40
#define NSTAGE    3

__global__ __launch_bounds__(256)
void tgemm_wmma(const __nv_bfloat16* __restrict__ A, const __nv_bfloat16* __restrict__ B,
                const float* __restrict__ bias, float* __restrict__ C,
                __nv_bfloat16* __restrict__ q2o,
                __nv_bfloat16* __restrict__ khlo, __nv_bfloat16* __restrict__ vhlo,
                int M, int N, int Kp, int mode) {
    extern __shared__ char sm[];
    const uint32_t sbase = smem_u32(sm);
    float* biasS = (float*)(sm + NSTAGE * STG_BYTES);

    const int tid = threadIdx.x;
    const int wid = tid >> 5;
    const int wm = wid >> 2;
    const int wn = wid & 3;
    const int row0 = blockIdx.y * 128;
    const int col0 = blockIdx.x * 128;

    if (mode == 0)
        for (int i = tid; i < 16 * 128; i += 256)
            biasS[i] = bias ? bias[col0 + (i & 127)] : 0.f;

    auto loadStage = [&](int s, int k0) {
        uint32_t ab = sbase + s * STG_BYTES;
        uint32_t bb = ab + STG_BYTES / 2;
#pragma unroll
        for (int p = 0; p < 2; ++p) {
            int i = tid + p * 256;
            int r = i >> 2, qq = i & 3;
            cpasync16s(ab + r * 80 + qq * 16,
                       (const char*)A + (((size_t)(row0 + r)) * Kp + k0 + qq * 8) * 2);
            cpasync16s(bb + r * 80 + qq * 16,
                       (const char*)B + (((size_t)(col0 + r)) * Kp + k0 + qq * 8) * 2);
        }
    };

    wmma::fragment<wmma::accumulator, 16, 16, 16, float> acc[4][2];
    __syncthreads();
    if (mode == 0) {
#pragma unroll
        for (int i = 0; i < 4; ++i)
#pragma unroll
            for (int j = 0; j < 2; ++j)
                wmma::load_matrix_sync(acc[i][j], &biasS[wn * 32 + j * 16], 128, wmma::mem_row_major);
    } else {
#pragma unroll
        for (int i = 0; i < 4; ++i)
#pragma unroll
            for (int j = 0; j < 2; ++j)
                wmma::fill_fragment(acc[i][j], 0.f);
    }

    loadStage(0, 0); cp_commit();
    loadStage(1, 32); cp_commit();

    const int nst = Kp / 32;
    for (int st = 0; st < nst; ++st) {
        if (st == nst - 1) cp_wait0(); else cp_wait1();
        __syncthreads();
        if (st + 2 < nst) { loadStage((st + 2) % NSTAGE, (st + 2) * 32); cp_commit(); }

        const __nv_bfloat16* as = (const __nv_bfloat16*)(sm + (st % NSTAGE) * STG_BYTES);
        const __nv_bfloat16* bs = as + STG_BYTES / 4;

#pragma unroll
        for (int kk = 0; kk < 2; ++kk) {
            wmma::fragment<wmma::matrix_a, 16, 16, 16, __nv_bfloat16, wmma::row_major> af[4];
            wmma::fragment<wmma::matrix_b, 16, 16, 16, __nv_bfloat16, wmma::col_major> bfr[2];
#pragma unroll
            for (int i = 0; i < 4; ++i)
                wmma::load_matrix_sync(af[i], as + (wm * 64 + i * 16) * LDS_ROW + kk * 16, LDS_ROW);
#pragma unroll
            for (int j = 0; j < 2; ++j)
                wmma::load_matrix_sync(bfr[j], bs + (wn * 32 + j * 16) * LDS_ROW + kk * 16, LDS_ROW);
#pragma unroll
            for (int i = 0; i < 4; ++i)
#pragma unroll
                for (int j = 0; j < 2; ++j)
                    wmma::mma_sync(acc[i][j], af[i], bfr[j], acc[i][j]);
        }
    }

    if (mode == 0) {
#pragma unroll
        for (int i = 0; i < 4; ++i)
#pragma unroll
            for (int j = 0; j < 2; ++j)
                wmma::store_matrix_sync(&C[(size_t)(row0 + wm * 64 + i * 16) * N + col0 + wn * 32 + j * 16],
                                        acc[i][j], N, wmma::mem_row_major);
        return;
    }

    __syncthreads();
    float* Cs = (float*)sm;   // [128][132]
#pragma unroll
    for (int i = 0; i < 4; ++i)
#pragma unroll
        for (int j = 0; j < 2; ++j)
            wmma::store_matrix_sync(&Cs[(size_t)(wm * 64 + i * 16) * 132 + wn * 32 + j * 16],
                                    acc[i][j], 132, wmma::mem_row_major);
    __syncthreads();

    if (mode == 1) {
        for (int idx = tid; idx < 128 * 128; idx += 256) {
            int r = idx >> 7, c = idx & 127;
            float v = Cs[r * 132 + c];
            __nv_bfloat16 hv, lv; split1(v, hv, lv);
            int bt = row0 + r, gc = col0 + c;
            int b = bt >> 10, t = bt & 1023;
            int h = gc >> 6, cc = gc & 63;
            __nv_bfloat16* o = q2o + (((size_t)(b * NHEAD + h) * TLEN + t)) * 128 + cc;
            o[0] = hv; o[64] = lv;
        }
    } else {
        for (int idx = tid; idx < 128 * 128; idx += 256) {
            int r = idx >> 7, c = idx & 127;
            float v = Cs[r * 132 + c];
            __nv_bfloat16 hv, lv; split1(v, hv, lv);
            int rg = row0 + r, gc = col0 + c;
            int b = rg >> 11, m = rg & 2047;
            __nv_bfloat16* dst = (gc < DMODEL) ? khlo : vhlo;
            int gcl = (gc < DMODEL) ? gc : gc - DMODEL;
            int h = gcl >> 6, cc = gcl & 63;
            __nv_bfloat16* o = dst + (((size_t)(b * NHEAD + h) * JDIM + m)) * 128 + cc;
            o[0] = hv; o[64] = lv;
        }
    }
}

// ---------------------------------------------------------------------------
// FA2-style flash attention: 128 q-rows/CTA, 8 warps x 16 rows x 64 cols.
// S and PV on raw mma.sync with register fragments; softmax in registers
// (quad shuffles); P repacked C->A in registers. Rel-R via per-warp mma into
// a bf16 ring (same-warp produce/consume). K/V double-buffered, W ring-4.
// ---------------------------------------------------------------------------
struct __align__(16) AttnW {
    __nv_bfloat16 Q2s[128][136];      // [Qh(64) | Ql(64)]
    __nv_bfloat16 Khl[2][64][136];    // [Kh | Kl]
    __nv_bfloat16 Vhl[2][64][136];    // [Vh | Vl]
    __nv_bfloat16 Wh[4][64][72];      // W span ring (hi only), slot = (u>>6)&3
    __nv_bfloat16 Rx[3][128][72];     // rel scores ring, slot = (u>>6)%3
};

__device__ __forceinline__ void aw_pf_K(AttnW& S, int bb, const __nv_bfloat16* __restrict__ khl,
                                        size_t bh, int m0, int tid) {
#pragma unroll
    for (int p = 0; p < 4; ++p) {
        int i = tid + p * 256;
        int r = i >> 4, c = i & 15;
        cpasync16(&S.Khl[bb][r][c * 8], khl + (bh * JDIM + (size_t)(m0 + r)) * 128 + c * 8);
    }
}
__device__ __forceinline__ void aw_pf_V(AttnW& S, int bb, const __nv_bfloat16* __restrict__ vhl,
                                        size_t bh, int m0, int tid) {
#pragma unroll
    for (int p = 0; p < 4; ++p) {
        int i = tid + p * 256;
        int r = i >> 4, c = i & 15;
        cpasync16(&S.Vhl[bb][r][c * 8], vhl + (bh * JDIM + (size_t)(m0 + r)) * 128 + c * 8);
    }
}
// load 64 rows x 64 bf16 (hi) at u-base ub into ring slot (ub>>6)&3
__device__ __forceinline__ void aw_pf_W(AttnW& S, const __nv_bfloat16* __restrict__ rel2,
                                        int h, int ub, int tid) {
    int slot = (ub >> 6) & 3;
#pragma unroll
    for (int p = 0; p < 2; ++p) {
        int i = tid + p * 256;
        int o = i >> 3, c = i & 7;
        int u = ub + o; if (u > JDIM - 1) u = JDIM - 1;
        cpasync16(&S.Wh[slot][o][c * 8], rel2 + ((size_t)h * JDIM + u) * 64 + c * 8);
    }
}

__global__ __launch_bounds__(256, 1)
void attn_mma(const __nv_bfloat16* __restrict__ q2,
              const __nv_bfloat16* __restrict__ khl,
              const __nv_bfloat16* __restrict__ vhl,
              const __nv_bfloat16* __restrict__ rel2,
              __nv_bfloat16* __restrict__ a2) {
    extern __shared__ char smem_raw[];
    AttnW& S = *reinterpret_cast<AttnW*>(smem_raw);

    const int b  = blockIdx.z;
    const int h  = blockIdx.y;
    const int rb = (int)gridDim.x - 1 - (int)blockIdx.x;   // long blocks first
    const int r0 = rb * 128;
    const size_t bh = (size_t)(b * NHEAD + h);
    const int tid = threadIdx.x;
    const int wid = tid >> 5;
    const int lane = tid & 31;
    const int g   = lane >> 2;          // quad group = row within 8
    const int tig = lane & 3;           // col pair within 8
    const int rowbase = wid * 16;       // warp's 16 q-rows
    const int rl1 = rowbase + g;        // local rows owned by this thread
    const int rl2 = rl1 + 8;

    // ---- initial loads: Q (128x128), K/V tile 0, W slots for u-window ----
#pragma unroll
    for (int p = 0; p < 8; ++p) {
        int i = tid + p * 256;
        int r = i >> 4, c = i & 15;
        cpasync16(&S.Q2s[r][c * 8],
                  q2 + (bh * TLEN + (size_t)(r0 + r)) * 128 + c * 8);
    }
    aw_pf_K(S, 0, khl, bh, 0, tid);
    aw_pf_V(S, 0, vhl, bh, 0, tid);
    const int ubase0 = 896 - r0;        // >= 0 (r0 <= 896), 64-aligned
    aw_pf_W(S, rel2, h, ubase0,        tid);
    aw_pf_W(S, rel2, h, ubase0 + 64,   tid);
    aw_pf_W(S, rel2, h, ubase0 + 128,  tid);
    cp_commit();

    float accf[8][4];
#pragma unroll
    for (int i = 0; i < 8; ++i)
#pragma unroll
        for (int j = 0; j < 4; ++j) accf[i][j] = 0.f;
    float mreg[2] = {-1e30f, -1e30f};
    float lreg[2] = {0.f, 0.f};

    uint32_t aQh[4][4], aQl[4][4];      // Q A-fragments, loaded once

    const int ntiles = min(32, 2 * rb + 18);

    for (int mt = 0; mt < ntiles; ++mt) {
        const int cur = mt & 1;
        const int prv = cur ^ 1;
        const int m0  = mt * 64;

        cp_wait0();
        __syncthreads();                 // K/V/W for this tile ready

        if (mt == 0) {
            // Q fragments: rows rowbase..+15
            int s = lane >> 3, rr2 = lane & 7;
            int arow = rowbase + (s & 1) * 8 + rr2;
            int acol = (s >> 1) * 8;
#pragma unroll
            for (int k16 = 0; k16 < 4; ++k16) {
                ldmx4(aQh[k16], smem_u32(&S.Q2s[arow][acol + k16 * 16]));
                ldmx4(aQl[k16], smem_u32(&S.Q2s[arow][64 + acol + k16 * 16]));
            }
        }

        if (mt + 1 < ntiles) {
            aw_pf_K(S, prv, khl, bh, m0 + 64, tid);
            aw_pf_V(S, prv, vhl, bh, m0 + 64, tid);
            cp_commit();
        }

        // ---- R: compute new slot(s) = Qh @ Wh^T for warp's 16 rows ----
        {
            const int nR = (mt == 0) ? 3 : 1;
#pragma unroll
            for (int rr = 0; rr < nR; ++rr) {
                int ub = (mt == 0) ? (ubase0 + 64 * rr) : (ubase0 + 64 * (mt + 2));
                int wslot = (ub >> 6) & 3;
                int rslot = (ub >> 6) % 3;
#pragma unroll
                for (int nt = 0; nt < 8; ++nt) {
                    float c[4] = {0.f, 0.f, 0.f, 0.f};
#pragma unroll
                    for (int k16 = 0; k16 < 4; ++k16) {
                        uint32_t bw[2];
                        ldmx2(bw, smem_u32(&S.Wh[wslot][nt * 8 + (lane & 7)]
                                                 [k16 * 16 + 8 * ((lane >> 3) & 1)]));
                        mma16816(c, aQh[k16], bw);
                    }
                    int colc = 8 * nt + 2 * tig;
                    *(__nv_bfloat162*)&S.Rx[rslot][rl1][colc] =
                        __halves2bfloat162(__float2bfloat16(c[0]), __float2bfloat16(c[1]));
                    *(__nv_bfloat162*)&S.Rx[rslot][rl2][colc] =
                        __halves2bfloat162(__float2bfloat16(c[2]), __float2bfloat16(c[3]));
                }
            }
        }
        __syncwarp();                    // R rows are same-warp; order st->ld

        // ---- S: 3 compensated passes into register fragments ----
        float sc[8][4];
#pragma unroll
        for (int nt = 0; nt < 8; ++nt) {
#pragma unroll
            for (int j = 0; j < 4; ++j) sc[nt][j] = 0.f;
#pragma unroll
            for (int k16 = 0; k16 < 4; ++k16) {
                uint32_t bkh[2], bkl[2];
                int krow = nt * 8 + (lane & 7);
                int kc = k16 * 16 + 8 * ((lane >> 3) & 1);
                ldmx2(bkh, smem_u32(&S.Khl[cur][krow][kc]));
                ldmx2(bkl, smem_u32(&S.Khl[cur][krow][64 + kc]));
                mma16816(sc[nt], aQh[k16], bkh);
                mma16816(sc[nt], aQl[k16], bkh);
                mma16816(sc[nt], aQh[k16], bkl);
            }
        }

        // ---- softmax in registers (rows rl1, rl2; quad reduction) ----
        uint32_t phx[2][8], plx[2][8];   // bf16x2 P values per row-set per nt
        float alpha[2];
#pragma unroll
        for (int ri = 0; ri < 2; ++ri) {
            const int rl = (ri == 0) ? rl1 : rl2;
            const int mlim = r0 + rl + MEMLEN - m0;
            const int ubase = m0 + 1023 - r0 - rl;
            float sv[8][2];
            float rmax = -1e30f;
#pragma unroll
            for (int nt = 0; nt < 8; ++nt) {
#pragma unroll
                for (int j = 0; j < 2; ++j) {
                    int mm = 8 * nt + 2 * tig + j;
                    int u = ubase + mm;
                    int slot = (u >> 6) % 3;
                    float rv = __bfloat162float(S.Rx[slot][rl][u & 63]);
                    float s = (sc[nt][2 * ri + j] + rv) * 0.125f;
                    if (mm > mlim) s = -1e30f;
                    sv[nt][j] = s;
                    rmax = fmaxf(rmax, s);
                }
            }
            rmax = fmaxf(rmax, __shfl_xor_sync(0xffffffffu, rmax, 1));
            rmax = fmaxf(rmax, __shfl_xor_sync(0xffffffffu, rmax, 2));
            float mnew = fmaxf(mreg[ri], rmax);
            alpha[ri] = __expf(mreg[ri] - mnew);
            float lsum = 0.f;
#pragma unroll
            for (int nt = 0; nt < 8; ++nt) {
                float p0 = __expf(sv[nt][0] - mnew);
                float p1 = __expf(sv[nt][1] - mnew);
                lsum += p0 + p1;
                __nv_bfloat16 h0 = __float2bfloat16(p0);
                __nv_bfloat16 h1 = __float2bfloat16(p1);
                phx[ri][nt] = packbf2(h0, h1);
                plx[ri][nt] = packbf2(__float2bfloat16(p0 - __bfloat162float(h0)),
                                      __float2bfloat16(p1 - __bfloat162float(h1)));
            }
            lsum += __shfl_xor_sync(0xffffffffu, lsum, 1);
            lsum += __shfl_xor_sync(0xffffffffu, lsum, 2);
            lreg[ri] = lreg[ri] * alpha[ri] + lsum;
            mreg[ri] = mnew;
        }

        // ---- PV: rescale accf, repack P C->A fragments, mma with V ----
#pragma unroll
        for (int nt = 0; nt < 8; ++nt) {
            accf[nt][0] *= alpha[0]; accf[nt][1] *= alpha[0];
            accf[nt][2] *= alpha[1]; accf[nt][3] *= alpha[1];
        }
        uint32_t aPh[4][4], aPl[4][4];
#pragma unroll
        for (int kk = 0; kk < 4; ++kk) {
            aPh[kk][0] = phx[0][2 * kk];     aPh[kk][1] = phx[1][2 * kk];
            aPh[kk][2] = phx[0][2 * kk + 1]; aPh[kk][3] = phx[1][2 * kk + 1];
            aPl[kk][0] = plx[0][2 * kk];     aPl[kk][1] = plx[1][2 * kk];
            aPl[kk][2] = plx[0][2 * kk + 1]; aPl[kk][3] = plx[1][2 * kk + 1];
        }
        {
            int s = (lane >> 3) & 1, rr2 = lane & 7;
#pragma unroll
            for (int k16 = 0; k16 < 4; ++k16) {
                int vrow = k16 * 16 + s * 8 + rr2;
#pragma unroll
                for (int nt = 0; nt < 8; ++nt) {
                    uint32_t bhv[2], blv[2];
                    ldmx2t(bhv, smem_u32(&S.Vhl[cur][vrow][nt * 8]));
                    ldmx2t(blv, smem_u32(&S.Vhl[cur][vrow][64 + nt * 8]));
                    mma16816(accf[nt], aPh[k16], bhv);
                    mma16816(accf[nt], aPl[k16], bhv);
                    mma16816(accf[nt], aPh[k16], blv);
                }
            }
        }

        // ---- W prefetch for next tile's R slot ----
        if (mt + 1 < ntiles) {
            aw_pf_W(S, rel2, h, ubase0 + 64 * (mt + 3), tid);
            cp_commit();
        }
    }

    // ---- epilogue: write a2 [row][3072] = [h | l | h] from fragments ----
    {
        float inv1 = 1.f / lreg[0];
        float inv2 = 1.f / lreg[1];
        size_t grow1 = (size_t)(b * TLEN + r0 + rl1) * KP3;
        size_t grow2 = (size_t)(b * TLEN + r0 + rl2) * KP3;
#pragma unroll
        for (int nt = 0; nt < 8; ++nt) {
            int col = h * 64 + 8 * nt + 2 * tig;
            float v0 = accf[nt][0] * inv1, v1 = accf[nt][1] * inv1;
            float v2 = accf[nt][2] * inv2, v3 = accf[nt][3] * inv2;
            __nv_bfloat16 h0, l0, h1, l1, h2, l2, h3, l3;
            split1(v0, h0, l0); split1(v1, h1, l1);
            split1(v2, h2, l2); split1(v3, h3, l3);
            __nv_bfloat16* o1 = a2 + grow1 + col;
            __nv_bfloat16* o2 = a2 + grow2 + col;
            *(__nv_bfloat162*)(o1)              = __halves2bfloat162(h0, h1);
            *(__nv_bfloat162*)(o1 + DMODEL)     = __halves2bfloat162(l0, l1);
            *(__nv_bfloat162*)(o1 + 2 * DMODEL) = __halves2bfloat162(h0, h1);
            *(__nv_bfloat162*)(o2)              = __halves2bfloat162(h2, h3);
            *(__nv_bfloat162*)(o2 + DMODEL)     = __halves2bfloat162(l2, l3);
            *(__nv_bfloat162*)(o2 + 2 * DMODEL) = __halves2bfloat162(h2, h3);
        }
    }
}

// ---------------------------------------------------------------------------
extern "C" void kernel_launch(void* const* d_in, const int* in_sizes, int n_in,
                              void* d_out, int out_size) {
    const float* x    = (const float*)d_in[0];
    const float* mem  = (const float*)d_in[1];
    const float* wq   = (const float*)d_in[2];
    const float* wkv  = (const float*)d_in[3];
    const float* wo   = (const float*)d_in[4];
    const float* bo   = (const float*)d_in[5];
    const float* relw = (const float*)d_in[6];

    float* out_main = (float*)d_out;
    float* mem_next = out_main + (size_t)BATCH * TLEN * DMODEL;

    __nv_bfloat16 *x2, *kvin2, *a2, *wq2, *wkv2, *wo2, *q2, *rel2, *khl, *vhl;
    cudaGetSymbolAddress((void**)&x2,    g_x2);
    cudaGetSymbolAddress((void**)&kvin2, g_kvin2);
    cudaGetSymbolAddress((void**)&a2,    g_a2);
    cudaGetSymbolAddress((void**)&wq2,   g_wq2);
    cudaGetSymbolAddress((void**)&wkv2,  g_wkv2);
    cudaGetSymbolAddress((void**)&wo2,   g_wo2);
    cudaGetSymbolAddress((void**)&q2,    g_q2);
    cudaGetSymbolAddress((void**)&rel2,  g_rel2);
    cudaGetSymbolAddress((void**)&khl,   g_khl);
    cudaGetSymbolAddress((void**)&vhl,   g_vhl);

    const int TG_SMEM = NSTAGE * STG_BYTES + 16 * 128 * 4;    // 69632
    const int AW_SMEM = (int)sizeof(AttnW);
    cudaFuncSetAttribute(tgemm_wmma, cudaFuncAttributeMaxDynamicSharedMemorySize, TG_SMEM);
    cudaFuncSetAttribute(attn_mma,   cudaFuncAttributeMaxDynamicSharedMemorySize, AW_SMEM);

    // operand prep
    {
        size_t tot = (size_t)BATCH * TLEN * 256;
        split3_rows<<<(unsigned)((tot + 255) / 256), 256>>>(x, x2, tot);
    }
    {
        size_t tot = (size_t)BATCH * JDIM * 256;
        build_kvin_split3<<<(unsigned)((tot + 255) / 256), 256>>>(x, mem, kvin2);
    }
    transpose_split3<<<dim3(DMODEL / 32, DMODEL / 32), dim3(32, 8)>>>(wq, wq2, DMODEL);
    transpose_split3<<<dim3(2 * DMODEL / 32, DMODEL / 32), dim3(32, 8)>>>(wkv, wkv2, 2 * DMODEL);
    transpose_split3<<<dim3(DMODEL / 32, DMODEL / 32), dim3(32, 8)>>>(wo, wo2, DMODEL);
    {
        size_t tot = (size_t)JDIM * NHEAD * 16;
        build_rel2k<<<(unsigned)((tot + 255) / 256), 256>>>(relw, rel2);
    }

    // q-proj -> q2 (mode 1)
    tgemm_wmma<<<dim3(DMODEL / 128, BATCH * TLEN / 128), 256, TG_SMEM>>>(
        x2, wq2, nullptr, nullptr, q2, nullptr, nullptr, BATCH * TLEN, DMODEL, KP3, 1);
    // kv-proj -> khl/vhl (mode 2)
    tgemm_wmma<<<dim3(2 * DMODEL / 128, BATCH * JDIM / 128), 256, TG_SMEM>>>(
        kvin2, wkv2, nullptr, nullptr, nullptr, khl, vhl, BATCH * JDIM, 2 * DMODEL, KP3, 2);
    // flash attention -> a2 (128 q-rows per block)
    attn_mma<<<dim3(TLEN / 128, NHEAD, BATCH), 256, AW_SMEM>>>(q2, khl, vhl, rel2, a2);
    // out = attn @ wo + bo (mode 0)
    tgemm_wmma<<<dim3(DMODEL / 128, BATCH * TLEN / 128), 256, TG_SMEM>>>(
        a2, wo2, bo, out_main, nullptr, nullptr, nullptr, BATCH * TLEN, DMODEL, KP3, 0);
    // mem_next = x
    {
        size_t n4 = (size_t)BATCH * TLEN * DMODEL / 4;
        copy_x<<<(unsigned)((n4 + 255) / 256), 256>>>(x, mem_next);
    }
}

// round 15
// speedup vs baseline: 1.2776x; 1.0495x over previous
#include <cuda_runtime.h>
#include <cuda_bf16.h>
#include <mma.h>
#include <cstddef>
#include <cstdint>

using namespace nvcuda;

#define BATCH   4
#define TLEN    1024
#define MEMLEN  1024
#define JDIM    2048
#define DMODEL  1024
#define NHEAD   16
#define DHEAD   64
#define KP3     3072      // 3 * DMODEL (compensated K)

// -------- scratch (static __device__ globals; cudaMalloc is forbidden) ------
__device__ __nv_bfloat16 g_kvin2[(size_t)BATCH * JDIM * KP3];    // [h|l|h]
__device__ __nv_bfloat16 g_a2   [(size_t)BATCH * TLEN * KP3];    // [h|l|h]
__device__ __nv_bfloat16 g_wq2  [(size_t)DMODEL * KP3];          // [h|h|l] (transposed)
__device__ __nv_bfloat16 g_wkv2 [(size_t)2 * DMODEL * KP3];      // [h|h|l]
__device__ __nv_bfloat16 g_wo2  [(size_t)DMODEL * KP3];          // [h|h|l]
__device__ __nv_bfloat16 g_q2   [(size_t)BATCH * NHEAD * TLEN * 128];  // [Qh|Ql]
__device__ __nv_bfloat16 g_rel2 [(size_t)NHEAD * JDIM * 64];           // hi only
__device__ __nv_bfloat16 g_khl  [(size_t)BATCH * NHEAD * JDIM * 128];  // [Kh|Kl]
__device__ __nv_bfloat16 g_vhl  [(size_t)BATCH * NHEAD * JDIM * 128];  // [Vh|Vl]

// ---------------------------------------------------------------------------
__device__ __forceinline__ uint32_t smem_u32(const void* p) {
    uint32_t a;
    asm("{ .reg .u64 t; cvta.to.shared.u64 t, %1; cvt.u32.u64 %0, t; }" : "=r"(a) : "l"(p));
    return a;
}
__device__ __forceinline__ void cpasync16s(uint32_t saddr, const void* gsrc) {
    asm volatile("cp.async.cg.shared.global [%0], [%1], 16;\n" :: "r"(saddr), "l"(gsrc));
}
__device__ __forceinline__ void cpasync16(void* smem_dst, const void* gsrc) {
    cpasync16s((uint32_t)__cvta_generic_to_shared(smem_dst), gsrc);
}
__device__ __forceinline__ void cp_commit() { asm volatile("cp.async.commit_group;\n"); }
__device__ __forceinline__ void cp_wait0()  { asm volatile("cp.async.wait_group 0;\n"); }
__device__ __forceinline__ void cp_wait1()  { asm volatile("cp.async.wait_group 1;\n"); }

__device__ __forceinline__ void split1(float v, __nv_bfloat16& h, __nv_bfloat16& l) {
    h = __float2bfloat16(v);
    l = __float2bfloat16(v - __bfloat162float(h));
}
__device__ __forceinline__ uint32_t packbf2(__nv_bfloat16 lo, __nv_bfloat16 hi) {
    return (uint32_t)__bfloat16_as_ushort(lo) | ((uint32_t)__bfloat16_as_ushort(hi) << 16);
}

// raw tensor-core primitives (documented PTX layouts, sm_80+)
__device__ __forceinline__ void ldmx4(uint32_t* r, uint32_t addr) {
    asm volatile("ldmatrix.sync.aligned.m8n8.x4.shared.b16 {%0,%1,%2,%3}, [%4];"
                 : "=r"(r[0]), "=r"(r[1]), "=r"(r[2]), "=r"(r[3]) : "r"(addr));
}
__device__ __forceinline__ void ldmx2(uint32_t* r, uint32_t addr) {
    asm volatile("ldmatrix.sync.aligned.m8n8.x2.shared.b16 {%0,%1}, [%2];"
                 : "=r"(r[0]), "=r"(r[1]) : "r"(addr));
}
__device__ __forceinline__ void ldmx2t(uint32_t* r, uint32_t addr) {
    asm volatile("ldmatrix.sync.aligned.m8n8.x2.trans.shared.b16 {%0,%1}, [%2];"
                 : "=r"(r[0]), "=r"(r[1]) : "r"(addr));
}
__device__ __forceinline__ void mma16816(float* c, const uint32_t* a, const uint32_t* b) {
    asm volatile("mma.sync.aligned.m16n8k16.row.col.f32.bf16.bf16.f32 "
                 "{%0,%1,%2,%3},{%4,%5,%6,%7},{%8,%9},{%0,%1,%2,%3};"
                 : "+f"(c[0]), "+f"(c[1]), "+f"(c[2]), "+f"(c[3])
                 : "r"(a[0]), "r"(a[1]), "r"(a[2]), "r"(a[3]), "r"(b[0]), "r"(b[1]));
}

// ---------------------------------------------------------------------------
// prep kernels
// ---------------------------------------------------------------------------
__global__ void build_kvin_split3(const float* __restrict__ x, const float* __restrict__ mem,
                                  __nv_bfloat16* __restrict__ out) {
    size_t i = (size_t)blockIdx.x * blockDim.x + threadIdx.x;
    const size_t total = (size_t)BATCH * JDIM * 256;
    if (i >= total) return;
    size_t r = i >> 8;
    int c4 = (int)(i & 255) * 4;
    size_t b = r / JDIM, m = r % JDIM;
    float4 v;
    if (m < MEMLEN) v = *(const float4*)&mem[(b * MEMLEN + m) * DMODEL + c4];
    else            v = *(const float4*)&x  [(b * TLEN + (m - MEMLEN)) * DMODEL + c4];
    __nv_bfloat16 h[4], l[4];
    split1(v.x, h[0], l[0]); split1(v.y, h[1], l[1]);
    split1(v.z, h[2], l[2]); split1(v.w, h[3], l[3]);
    __nv_bfloat16* o = out + r * KP3;
    __nv_bfloat162 hp0 = __halves2bfloat162(h[0], h[1]), hp1 = __halves2bfloat162(h[2], h[3]);
    __nv_bfloat162 lp0 = __halves2bfloat162(l[0], l[1]), lp1 = __halves2bfloat162(l[2], l[3]);
    *(__nv_bfloat162*)(o + c4)              = hp0; *(__nv_bfloat162*)(o + c4 + 2)              = hp1;
    *(__nv_bfloat162*)(o + DMODEL + c4)     = lp0; *(__nv_bfloat162*)(o + DMODEL + c4 + 2)     = lp1;
    *(__nv_bfloat162*)(o + 2 * DMODEL + c4) = hp0; *(__nv_bfloat162*)(o + 2 * DMODEL + c4 + 2) = hp1;
}

__global__ void transpose_split3(const float* __restrict__ W, __nv_bfloat16* __restrict__ T2, int N) {
    __shared__ float t[32][33];
    int k0 = blockIdx.y * 32, n0 = blockIdx.x * 32;
    int tx = threadIdx.x, ty = threadIdx.y;
#pragma unroll
    for (int i = 0; i < 32; i += 8)
        t[ty + i][tx] = W[(size_t)(k0 + ty + i) * N + n0 + tx];
    __syncthreads();
#pragma unroll
    for (int i = 0; i < 32; i += 8) {
        float v = t[tx][ty + i];
        int n = n0 + ty + i, k = k0 + tx;
        __nv_bfloat16 h, l;
        split1(v, h, l);
        __nv_bfloat16* o = T2 + (size_t)n * KP3;
        o[k] = h; o[DMODEL + k] = h; o[2 * DMODEL + k] = l;
    }
}

__global__ void build_rel2k(const float* __restrict__ rel, __nv_bfloat16* __restrict__ rel2) {
    size_t i = (size_t)blockIdx.x * blockDim.x + threadIdx.x;
    const size_t total = (size_t)JDIM * NHEAD * 16;
    if (i >= total) return;
    int c4 = (int)(i & 15) * 4;
    int h  = (int)(i >> 4) & 15;
    int u  = (int)(i >> 8);
    float4 v = *(const float4*)&rel[((size_t)u * NHEAD + h) * DHEAD + c4];
    __nv_bfloat16* o = rel2 + ((size_t)h * JDIM + u) * 64;
    *(__nv_bfloat162*)(o + c4)     = __halves2bfloat162(__float2bfloat16(v.x), __float2bfloat16(v.y));
    *(__nv_bfloat162*)(o + c4 + 2) = __halves2bfloat162(__float2bfloat16(v.z), __float2bfloat16(v.w));
}

__global__ void copy_x(const float* __restrict__ x, float* __restrict__ dst) {
    size_t i = (size_t)blockIdx.x * blockDim.x + threadIdx.x;
    const size_t total = (size_t)BATCH * TLEN * DMODEL / 4;
    if (i < total) ((float4*)dst)[i] = ((const float4*)x)[i];
}

// ---------------------------------------------------------------------------
// wmma bf16 GEMM, 128x128 tile, 3-stage cp.async, 2 CTAs/SM.
// mode 0: C = A@B^T + bias ; mode 1: q-proj -> q2 ; mode 2: kv-proj -> khl/vhl
// aremap: A rows are x rows embedded in kvin2 (row -> row + (row>>10)*1024 + 1024)
// ---------------------------------------------------------------------------
#define STG_BYTES 20480
#define LDS_ROW   40
#define NSTAGE    3

__global__ __launch_bounds__(256, 2)
void tgemm_wmma(const __nv_bfloat16* __restrict__ A, const __nv_bfloat16* __restrict__ B,
                const float* __restrict__ bias, float* __restrict__ C,
                __nv_bfloat16* __restrict__ q2o,
                __nv_bfloat16* __restrict__ khlo, __nv_bfloat16* __restrict__ vhlo,
                int M, int N, int Kp, int mode, int aremap) {
    extern __shared__ char sm[];
    const uint32_t sbase = smem_u32(sm);
    float* biasS = (float*)(sm + NSTAGE * STG_BYTES);

    const int tid = threadIdx.x;
    const int wid = tid >> 5;
    const int wm = wid >> 2;
    const int wn = wid & 3;
    const int row0 = blockIdx.y * 128;
    const int col0 = blockIdx.x * 128;

    // A base row (x rows live inside kvin2 when aremap)
    const int arow0 = aremap ? (row0 + ((row0 >> 10) + 1) * 1024) : row0;
    const __nv_bfloat16* Ap = A + (size_t)arow0 * Kp;

    if (mode == 0)
        for (int i = tid; i < 16 * 128; i += 256)
            biasS[i] = bias ? bias[col0 + (i & 127)] : 0.f;

    auto loadStage = [&](int s, int k0) {
        uint32_t ab = sbase + s * STG_BYTES;
        uint32_t bb = ab + STG_BYTES / 2;
#pragma unroll
        for (int p = 0; p < 2; ++p) {
            int i = tid + p * 256;
            int r = i >> 2, qq = i & 3;
            cpasync16s(ab + r * 80 + qq * 16,
                       (const char*)Ap + (((size_t)r) * Kp + k0 + qq * 8) * 2);
            cpasync16s(bb + r * 80 + qq * 16,
                       (const char*)B + (((size_t)(col0 + r)) * Kp + k0 + qq * 8) * 2);
        }
    };

    wmma::fragment<wmma::accumulator, 16, 16, 16, float> acc[4][2];
    __syncthreads();
    if (mode == 0) {
#pragma unroll
        for (int i = 0; i < 4; ++i)
#pragma unroll
            for (int j = 0; j < 2; ++j)
                wmma::load_matrix_sync(acc[i][j], &biasS[wn * 32 + j * 16], 128, wmma::mem_row_major);
    } else {
#pragma unroll
        for (int i = 0; i < 4; ++i)
#pragma unroll
            for (int j = 0; j < 2; ++j)
                wmma::fill_fragment(acc[i][j], 0.f);
    }

    loadStage(0, 0); cp_commit();
    loadStage(1, 32); cp_commit();

    const int nst = Kp / 32;
    for (int st = 0; st < nst; ++st) {
        if (st == nst - 1) cp_wait0(); else cp_wait1();
        __syncthreads();
        if (st + 2 < nst) { loadStage((st + 2) % NSTAGE, (st + 2) * 32); cp_commit(); }

        const __nv_bfloat16* as = (const __nv_bfloat16*)(sm + (st % NSTAGE) * STG_BYTES);
        const __nv_bfloat16* bs = as + STG_BYTES / 4;

#pragma unroll
        for (int kk = 0; kk < 2; ++kk) {
            wmma::fragment<wmma::matrix_a, 16, 16, 16, __nv_bfloat16, wmma::row_major> af[4];
            wmma::fragment<wmma::matrix_b, 16, 16, 16, __nv_bfloat16, wmma::col_major> bfr[2];
#pragma unroll
            for (int i = 0; i < 4; ++i)
                wmma::load_matrix_sync(af[i], as + (wm * 64 + i * 16) * LDS_ROW + kk * 16, LDS_ROW);
#pragma unroll
            for (int j = 0; j < 2; ++j)
                wmma::load_matrix_sync(bfr[j], bs + (wn * 32 + j * 16) * LDS_ROW + kk * 16, LDS_ROW);
#pragma unroll
            for (int i = 0; i < 4; ++i)
#pragma unroll
                for (int j = 0; j < 2; ++j)
                    wmma::mma_sync(acc[i][j], af[i], bfr[j], acc[i][j]);
        }
    }

    if (mode == 0) {
#pragma unroll
        for (int i = 0; i < 4; ++i)
#pragma unroll
            for (int j = 0; j < 2; ++j)
                wmma::store_matrix_sync(&C[(size_t)(row0 + wm * 64 + i * 16) * N + col0 + wn * 32 + j * 16],
                                        acc[i][j], N, wmma::mem_row_major);
        return;
    }

    __syncthreads();
    float* Cs = (float*)sm;   // [128][132]
#pragma unroll
    for (int i = 0; i < 4; ++i)
#pragma unroll
        for (int j = 0; j < 2; ++j)
            wmma::store_matrix_sync(&Cs[(size_t)(wm * 64 + i * 16) * 132 + wn * 32 + j * 16],
                                    acc[i][j], 132, wmma::mem_row_major);
    __syncthreads();

    if (mode == 1) {
        // pairs of adjacent columns -> bf16x2 stores
        for (int idx = tid; idx < 128 * 64; idx += 256) {
            int r = idx >> 6, c2 = (idx & 63) * 2;
            float v0 = Cs[r * 132 + c2], v1 = Cs[r * 132 + c2 + 1];
            __nv_bfloat16 h0, l0, h1, l1;
            split1(v0, h0, l0); split1(v1, h1, l1);
            int bt = row0 + r, gc = col0 + c2;
            int b = bt >> 10, t = bt & 1023;
            int h = gc >> 6, cc = gc & 63;
            __nv_bfloat16* o = q2o + (((size_t)(b * NHEAD + h) * TLEN + t)) * 128 + cc;
            *(__nv_bfloat162*)(o)      = __halves2bfloat162(h0, h1);
            *(__nv_bfloat162*)(o + 64) = __halves2bfloat162(l0, l1);
        }
    } else {
        for (int idx = tid; idx < 128 * 64; idx += 256) {
            int r = idx >> 6, c2 = (idx & 63) * 2;
            float v0 = Cs[r * 132 + c2], v1 = Cs[r * 132 + c2 + 1];
            __nv_bfloat16 h0, l0, h1, l1;
            split1(v0, h0, l0); split1(v1, h1, l1);
            int rg = row0 + r, gc = col0 + c2;
            int b = rg >> 11, m = rg & 2047;
            __nv_bfloat16* dst = (gc < DMODEL) ? khlo : vhlo;
            int gcl = (gc < DMODEL) ? gc : gc - DMODEL;
            int h = gcl >> 6, cc = gcl & 63;
            __nv_bfloat16* o = dst + (((size_t)(b * NHEAD + h) * JDIM + m)) * 128 + cc;
            *(__nv_bfloat162*)(o)      = __halves2bfloat162(h0, h1);
            *(__nv_bfloat162*)(o + 64) = __halves2bfloat162(l0, l1);
        }
    }
}

// ---------------------------------------------------------------------------
// FA2-style flash attention (unchanged from round 14)
// ---------------------------------------------------------------------------
struct __align__(16) AttnW {
    __nv_bfloat16 Q2s[128][136];      // [Qh(64) | Ql(64)]
    __nv_bfloat16 Khl[2][64][136];    // [Kh | Kl]
    __nv_bfloat16 Vhl[2][64][136];    // [Vh | Vl]
    __nv_bfloat16 Wh[4][64][72];      // W span ring (hi only), slot = (u>>6)&3
    __nv_bfloat16 Rx[3][128][72];     // rel scores ring, slot = (u>>6)%3
};

__device__ __forceinline__ void aw_pf_K(AttnW& S, int bb, const __nv_bfloat16* __restrict__ khl,
                                        size_t bh, int m0, int tid) {
#pragma unroll
    for (int p = 0; p < 4; ++p) {
        int i = tid + p * 256;
        int r = i >> 4, c = i & 15;
        cpasync16(&S.Khl[bb][r][c * 8], khl + (bh * JDIM + (size_t)(m0 + r)) * 128 + c * 8);
    }
}
__device__ __forceinline__ void aw_pf_V(AttnW& S, int bb, const __nv_bfloat16* __restrict__ vhl,
                                        size_t bh, int m0, int tid) {
#pragma unroll
    for (int p = 0; p < 4; ++p) {
        int i = tid + p * 256;
        int r = i >> 4, c = i & 15;
        cpasync16(&S.Vhl[bb][r][c * 8], vhl + (bh * JDIM + (size_t)(m0 + r)) * 128 + c * 8);
    }
}
__device__ __forceinline__ void aw_pf_W(AttnW& S, const __nv_bfloat16* __restrict__ rel2,
                                        int h, int ub, int tid) {
    int slot = (ub >> 6) & 3;
#pragma unroll
    for (int p = 0; p < 2; ++p) {
        int i = tid + p * 256;
        int o = i >> 3, c = i & 7;
        int u = ub + o; if (u > JDIM - 1) u = JDIM - 1;
        cpasync16(&S.Wh[slot][o][c * 8], rel2 + ((size_t)h * JDIM + u) * 64 + c * 8);
    }
}

__global__ __launch_bounds__(256, 1)
void attn_mma(const __nv_bfloat16* __restrict__ q2,
              const __nv_bfloat16* __restrict__ khl,
              const __nv_bfloat16* __restrict__ vhl,
              const __nv_bfloat16* __restrict__ rel2,
              __nv_bfloat16* __restrict__ a2) {
    extern __shared__ char smem_raw[];
    AttnW& S = *reinterpret_cast<AttnW*>(smem_raw);

    const int b  = blockIdx.z;
    const int h  = blockIdx.y;
    const int rb = (int)gridDim.x - 1 - (int)blockIdx.x;   // long blocks first
    const int r0 = rb * 128;
    const size_t bh = (size_t)(b * NHEAD + h);
    const int tid = threadIdx.x;
    const int wid = tid >> 5;
    const int lane = tid & 31;
    const int g   = lane >> 2;
    const int tig = lane & 3;
    const int rowbase = wid * 16;
    const int rl1 = rowbase + g;
    const int rl2 = rl1 + 8;

#pragma unroll
    for (int p = 0; p < 8; ++p) {
        int i = tid + p * 256;
        int r = i >> 4, c = i & 15;
        cpasync16(&S.Q2s[r][c * 8],
                  q2 + (bh * TLEN + (size_t)(r0 + r)) * 128 + c * 8);
    }
    aw_pf_K(S, 0, khl, bh, 0, tid);
    aw_pf_V(S, 0, vhl, bh, 0, tid);
    const int ubase0 = 896 - r0;
    aw_pf_W(S, rel2, h, ubase0,        tid);
    aw_pf_W(S, rel2, h, ubase0 + 64,   tid);
    aw_pf_W(S, rel2, h, ubase0 + 128,  tid);
    cp_commit();

    float accf[8][4];
#pragma unroll
    for (int i = 0; i < 8; ++i)
#pragma unroll
        for (int j = 0; j < 4; ++j) accf[i][j] = 0.f;
    float mreg[2] = {-1e30f, -1e30f};
    float lreg[2] = {0.f, 0.f};

    uint32_t aQh[4][4], aQl[4][4];

    const int ntiles = min(32, 2 * rb + 18);

    for (int mt = 0; mt < ntiles; ++mt) {
        const int cur = mt & 1;
        const int prv = cur ^ 1;
        const int m0  = mt * 64;

        cp_wait0();
        __syncthreads();

        if (mt == 0) {
            int s = lane >> 3, rr2 = lane & 7;
            int arow = rowbase + (s & 1) * 8 + rr2;
            int acol = (s >> 1) * 8;
#pragma unroll
            for (int k16 = 0; k16 < 4; ++k16) {
                ldmx4(aQh[k16], smem_u32(&S.Q2s[arow][acol + k16 * 16]));
                ldmx4(aQl[k16], smem_u32(&S.Q2s[arow][64 + acol + k16 * 16]));
            }
        }

        if (mt + 1 < ntiles) {
            aw_pf_K(S, prv, khl, bh, m0 + 64, tid);
            aw_pf_V(S, prv, vhl, bh, m0 + 64, tid);
            cp_commit();
        }

        // ---- R: compute new slot(s) = Qh @ Wh^T for warp's 16 rows ----
        {
            const int nR = (mt == 0) ? 3 : 1;
#pragma unroll
            for (int rr = 0; rr < nR; ++rr) {
                int ub = (mt == 0) ? (ubase0 + 64 * rr) : (ubase0 + 64 * (mt + 2));
                int wslot = (ub >> 6) & 3;
                int rslot = (ub >> 6) % 3;
#pragma unroll
                for (int nt = 0; nt < 8; ++nt) {
                    float c[4] = {0.f, 0.f, 0.f, 0.f};
#pragma unroll
                    for (int k16 = 0; k16 < 4; ++k16) {
                        uint32_t bw[2];
                        ldmx2(bw, smem_u32(&S.Wh[wslot][nt * 8 + (lane & 7)]
                                                 [k16 * 16 + 8 * ((lane >> 3) & 1)]));
                        mma16816(c, aQh[k16], bw);
                    }
                    int colc = 8 * nt + 2 * tig;
                    *(__nv_bfloat162*)&S.Rx[rslot][rl1][colc] =
                        __halves2bfloat162(__float2bfloat16(c[0]), __float2bfloat16(c[1]));
                    *(__nv_bfloat162*)&S.Rx[rslot][rl2][colc] =
                        __halves2bfloat162(__float2bfloat16(c[2]), __float2bfloat16(c[3]));
                }
            }
        }
        __syncwarp();

        // ---- S: 3 compensated passes into register fragments ----
        float sc[8][4];
#pragma unroll
        for (int nt = 0; nt < 8; ++nt) {
#pragma unroll
            for (int j = 0; j < 4; ++j) sc[nt][j] = 0.f;
#pragma unroll
            for (int k16 = 0; k16 < 4; ++k16) {
                uint32_t bkh[2], bkl[2];
                int krow = nt * 8 + (lane & 7);
                int kc = k16 * 16 + 8 * ((lane >> 3) & 1);
                ldmx2(bkh, smem_u32(&S.Khl[cur][krow][kc]));
                ldmx2(bkl, smem_u32(&S.Khl[cur][krow][64 + kc]));
                mma16816(sc[nt], aQh[k16], bkh);
                mma16816(sc[nt], aQl[k16], bkh);
                mma16816(sc[nt], aQh[k16], bkl);
            }
        }

        // ---- softmax in registers (rows rl1, rl2; quad reduction) ----
        uint32_t phx[2][8], plx[2][8];
        float alpha[2];
#pragma unroll
        for (int ri = 0; ri < 2; ++ri) {
            const int rl = (ri == 0) ? rl1 : rl2;
            const int mlim = r0 + rl + MEMLEN - m0;
            const int ubase = m0 + 1023 - r0 - rl;
            float sv[8][2];
            float rmax = -1e30f;
#pragma unroll
            for (int nt = 0; nt < 8; ++nt) {
#pragma unroll
                for (int j = 0; j < 2; ++j) {
                    int mm = 8 * nt + 2 * tig + j;
                    int u = ubase + mm;
                    int slot = (u >> 6) % 3;
                    float rv = __bfloat162float(S.Rx[slot][rl][u & 63]);
                    float s = (sc[nt][2 * ri + j] + rv) * 0.125f;
                    if (mm > mlim) s = -1e30f;
                    sv[nt][j] = s;
                    rmax = fmaxf(rmax, s);
                }
            }
            rmax = fmaxf(rmax, __shfl_xor_sync(0xffffffffu, rmax, 1));
            rmax = fmaxf(rmax, __shfl_xor_sync(0xffffffffu, rmax, 2));
            float mnew = fmaxf(mreg[ri], rmax);
            alpha[ri] = __expf(mreg[ri] - mnew);
            float lsum = 0.f;
#pragma unroll
            for (int nt = 0; nt < 8; ++nt) {
                float p0 = __expf(sv[nt][0] - mnew);
                float p1 = __expf(sv[nt][1] - mnew);
                lsum += p0 + p1;
                __nv_bfloat16 h0 = __float2bfloat16(p0);
                __nv_bfloat16 h1 = __float2bfloat16(p1);
                phx[ri][nt] = packbf2(h0, h1);
                plx[ri][nt] = packbf2(__float2bfloat16(p0 - __bfloat162float(h0)),
                                      __float2bfloat16(p1 - __bfloat162float(h1)));
            }
            lsum += __shfl_xor_sync(0xffffffffu, lsum, 1);
            lsum += __shfl_xor_sync(0xffffffffu, lsum, 2);
            lreg[ri] = lreg[ri] * alpha[ri] + lsum;
            mreg[ri] = mnew;
        }

        // ---- PV: rescale accf, repack P C->A fragments, mma with V ----
#pragma unroll
        for (int nt = 0; nt < 8; ++nt) {
            accf[nt][0] *= alpha[0]; accf[nt][1] *= alpha[0];
            accf[nt][2] *= alpha[1]; accf[nt][3] *= alpha[1];
        }
        uint32_t aPh[4][4], aPl[4][4];
#pragma unroll
        for (int kk = 0; kk < 4; ++kk) {
            aPh[kk][0] = phx[0][2 * kk];     aPh[kk][1] = phx[1][2 * kk];
            aPh[kk][2] = phx[0][2 * kk + 1]; aPh[kk][3] = phx[1][2 * kk + 1];
            aPl[kk][0] = plx[0][2 * kk];     aPl[kk][1] = plx[1][2 * kk];
            aPl[kk][2] = plx[0][2 * kk + 1]; aPl[kk][3] = plx[1][2 * kk + 1];
        }
        {
            int s = (lane >> 3) & 1, rr2 = lane & 7;
#pragma unroll
            for (int k16 = 0; k16 < 4; ++k16) {
                int vrow = k16 * 16 + s * 8 + rr2;
#pragma unroll
                for (int nt = 0; nt < 8; ++nt) {
                    uint32_t bhv[2], blv[2];
                    ldmx2t(bhv, smem_u32(&S.Vhl[cur][vrow][nt * 8]));
                    ldmx2t(blv, smem_u32(&S.Vhl[cur][vrow][64 + nt * 8]));
                    mma16816(accf[nt], aPh[k16], bhv);
                    mma16816(accf[nt], aPl[k16], bhv);
                    mma16816(accf[nt], aPh[k16], blv);
                }
            }
        }

        if (mt + 1 < ntiles) {
            aw_pf_W(S, rel2, h, ubase0 + 64 * (mt + 3), tid);
            cp_commit();
        }
    }

    // ---- epilogue: write a2 [row][3072] = [h | l | h] from fragments ----
    {
        float inv1 = 1.f / lreg[0];
        float inv2 = 1.f / lreg[1];
        size_t grow1 = (size_t)(b * TLEN + r0 + rl1) * KP3;
        size_t grow2 = (size_t)(b * TLEN + r0 + rl2) * KP3;
#pragma unroll
        for (int nt = 0; nt < 8; ++nt) {
            int col = h * 64 + 8 * nt + 2 * tig;
            float v0 = accf[nt][0] * inv1, v1 = accf[nt][1] * inv1;
            float v2 = accf[nt][2] * inv2, v3 = accf[nt][3] * inv2;
            __nv_bfloat16 h0, l0, h1, l1, h2, l2, h3, l3;
            split1(v0, h0, l0); split1(v1, h1, l1);
            split1(v2, h2, l2); split1(v3, h3, l3);
            __nv_bfloat16* o1 = a2 + grow1 + col;
            __nv_bfloat16* o2 = a2 + grow2 + col;
            *(__nv_bfloat162*)(o1)              = __halves2bfloat162(h0, h1);
            *(__nv_bfloat162*)(o1 + DMODEL)     = __halves2bfloat162(l0, l1);
            *(__nv_bfloat162*)(o1 + 2 * DMODEL) = __halves2bfloat162(h0, h1);
            *(__nv_bfloat162*)(o2)              = __halves2bfloat162(h2, h3);
            *(__nv_bfloat162*)(o2 + DMODEL)     = __halves2bfloat162(l2, l3);
            *(__nv_bfloat162*)(o2 + 2 * DMODEL) = __halves2bfloat162(h2, h3);
        }
    }
}

// ---------------------------------------------------------------------------
extern "C" void kernel_launch(void* const* d_in, const int* in_sizes, int n_in,
                              void* d_out, int out_size) {
    const float* x    = (const float*)d_in[0];
    const float* mem  = (const float*)d_in[1];
    const float* wq   = (const float*)d_in[2];
    const float* wkv  = (const float*)d_in[3];
    const float* wo   = (const float*)d_in[4];
    const float* bo   = (const float*)d_in[5];
    const float* relw = (const float*)d_in[6];

    float* out_main = (float*)d_out;
    float* mem_next = out_main + (size_t)BATCH * TLEN * DMODEL;

    __nv_bfloat16 *kvin2, *a2, *wq2, *wkv2, *wo2, *q2, *rel2, *khl, *vhl;
    cudaGetSymbolAddress((void**)&kvin2, g_kvin2);
    cudaGetSymbolAddress((void**)&a2,    g_a2);
    cudaGetSymbolAddress((void**)&wq2,   g_wq2);
    cudaGetSymbolAddress((void**)&wkv2,  g_wkv2);
    cudaGetSymbolAddress((void**)&wo2,   g_wo2);
    cudaGetSymbolAddress((void**)&q2,    g_q2);
    cudaGetSymbolAddress((void**)&rel2,  g_rel2);
    cudaGetSymbolAddress((void**)&khl,   g_khl);
    cudaGetSymbolAddress((void**)&vhl,   g_vhl);

    const int TG_SMEM = NSTAGE * STG_BYTES + 16 * 128 * 4;    // 69632
    const int AW_SMEM = (int)sizeof(AttnW);
    cudaFuncSetAttribute(tgemm_wmma, cudaFuncAttributeMaxDynamicSharedMemorySize, TG_SMEM);
    cudaFuncSetAttribute(attn_mma,   cudaFuncAttributeMaxDynamicSharedMemorySize, AW_SMEM);

    // operand prep
    {
        size_t tot = (size_t)BATCH * JDIM * 256;
        build_kvin_split3<<<(unsigned)((tot + 255) / 256), 256>>>(x, mem, kvin2);
    }
    transpose_split3<<<dim3(DMODEL / 32, DMODEL / 32), dim3(32, 8)>>>(wq, wq2, DMODEL);
    transpose_split3<<<dim3(2 * DMODEL / 32, DMODEL / 32), dim3(32, 8)>>>(wkv, wkv2, 2 * DMODEL);
    transpose_split3<<<dim3(DMODEL / 32, DMODEL / 32), dim3(32, 8)>>>(wo, wo2, DMODEL);
    {
        size_t tot = (size_t)JDIM * NHEAD * 16;
        build_rel2k<<<(unsigned)((tot + 255) / 256), 256>>>(relw, rel2);
    }

    // q-proj -> q2 (mode 1); A = x rows inside kvin2 (aremap)
    tgemm_wmma<<<dim3(DMODEL / 128, BATCH * TLEN / 128), 256, TG_SMEM>>>(
        kvin2, wq2, nullptr, nullptr, q2, nullptr, nullptr, BATCH * TLEN, DMODEL, KP3, 1, 1);
    // kv-proj -> khl/vhl (mode 2)
    tgemm_wmma<<<dim3(2 * DMODEL / 128, BATCH * JDIM / 128), 256, TG_SMEM>>>(
        kvin2, wkv2, nullptr, nullptr, nullptr, khl, vhl, BATCH * JDIM, 2 * DMODEL, KP3, 2, 0);
    // flash attention -> a2 (128 q-rows per block)
    attn_mma<<<dim3(TLEN / 128, NHEAD, BATCH), 256, AW_SMEM>>>(q2, khl, vhl, rel2, a2);
    // out = attn @ wo + bo (mode 0)
    tgemm_wmma<<<dim3(DMODEL / 128, BATCH * TLEN / 128), 256, TG_SMEM>>>(
        a2, wo2, bo, out_main, nullptr, nullptr, nullptr, BATCH * TLEN, DMODEL, KP3, 0, 0);
    // mem_next = x
    {
        size_t n4 = (size_t)BATCH * TLEN * DMODEL / 4;
        copy_x<<<(unsigned)((n4 + 255) / 256), 256>>>(x, mem_next);
    }
}

// round 16
// speedup vs baseline: 1.2847x; 1.0055x over previous
#include <cuda_runtime.h>
#include <cuda_bf16.h>
#include <mma.h>
#include <cstddef>
#include <cstdint>

using namespace nvcuda;

#define BATCH   4
#define TLEN    1024
#define MEMLEN  1024
#define JDIM    2048
#define DMODEL  1024
#define NHEAD   16
#define DHEAD   64
#define KP3     3072      // logical compensated K (3 passes)
#define KP2     2048      // physical storage: [h | l]

// -------- scratch (static __device__ globals; cudaMalloc is forbidden) ------
__device__ __nv_bfloat16 g_kvin2[(size_t)BATCH * JDIM * KP2];    // [h|l]
__device__ __nv_bfloat16 g_a2   [(size_t)BATCH * TLEN * KP2];    // [h|l]
__device__ __nv_bfloat16 g_wq2  [(size_t)DMODEL * KP2];          // [h|l] (transposed)
__device__ __nv_bfloat16 g_wkv2 [(size_t)2 * DMODEL * KP2];      // [h|l]
__device__ __nv_bfloat16 g_wo2  [(size_t)DMODEL * KP2];          // [h|l]
__device__ __nv_bfloat16 g_q2   [(size_t)BATCH * NHEAD * TLEN * 128];  // [Qh|Ql] (x0.125)
__device__ __nv_bfloat16 g_rel2 [(size_t)NHEAD * JDIM * 64];           // hi only
__device__ __nv_bfloat16 g_khl  [(size_t)BATCH * NHEAD * JDIM * 128];  // [Kh|Kl]
__device__ __nv_bfloat16 g_vhl  [(size_t)BATCH * NHEAD * JDIM * 128];  // [Vh|Vl]

// ---------------------------------------------------------------------------
__device__ __forceinline__ uint32_t smem_u32(const void* p) {
    uint32_t a;
    asm("{ .reg .u64 t; cvta.to.shared.u64 t, %1; cvt.u32.u64 %0, t; }" : "=r"(a) : "l"(p));
    return a;
}
__device__ __forceinline__ void cpasync16s(uint32_t saddr, const void* gsrc) {
    asm volatile("cp.async.cg.shared.global [%0], [%1], 16;\n" :: "r"(saddr), "l"(gsrc));
}
__device__ __forceinline__ void cpasync16(void* smem_dst, const void* gsrc) {
    cpasync16s((uint32_t)__cvta_generic_to_shared(smem_dst), gsrc);
}
__device__ __forceinline__ void cp_commit() { asm volatile("cp.async.commit_group;\n"); }
__device__ __forceinline__ void cp_wait0()  { asm volatile("cp.async.wait_group 0;\n"); }
__device__ __forceinline__ void cp_wait1()  { asm volatile("cp.async.wait_group 1;\n"); }

__device__ __forceinline__ void split1(float v, __nv_bfloat16& h, __nv_bfloat16& l) {
    h = __float2bfloat16(v);
    l = __float2bfloat16(v - __bfloat162float(h));
}
__device__ __forceinline__ uint32_t packbf2(__nv_bfloat16 lo, __nv_bfloat16 hi) {
    return (uint32_t)__bfloat16_as_ushort(lo) | ((uint32_t)__bfloat16_as_ushort(hi) << 16);
}

// raw tensor-core primitives (documented PTX layouts, sm_80+)
__device__ __forceinline__ void ldmx4(uint32_t* r, uint32_t addr) {
    asm volatile("ldmatrix.sync.aligned.m8n8.x4.shared.b16 {%0,%1,%2,%3}, [%4];"
                 : "=r"(r[0]), "=r"(r[1]), "=r"(r[2]), "=r"(r[3]) : "r"(addr));
}
__device__ __forceinline__ void ldmx2(uint32_t* r, uint32_t addr) {
    asm volatile("ldmatrix.sync.aligned.m8n8.x2.shared.b16 {%0,%1}, [%2];"
                 : "=r"(r[0]), "=r"(r[1]) : "r"(addr));
}
__device__ __forceinline__ void ldmx2t(uint32_t* r, uint32_t addr) {
    asm volatile("ldmatrix.sync.aligned.m8n8.x2.trans.shared.b16 {%0,%1}, [%2];"
                 : "=r"(r[0]), "=r"(r[1]) : "r"(addr));
}
__device__ __forceinline__ void mma16816(float* c, const uint32_t* a, const uint32_t* b) {
    asm volatile("mma.sync.aligned.m16n8k16.row.col.f32.bf16.bf16.f32 "
                 "{%0,%1,%2,%3},{%4,%5,%6,%7},{%8,%9},{%0,%1,%2,%3};"
                 : "+f"(c[0]), "+f"(c[1]), "+f"(c[2]), "+f"(c[3])
                 : "r"(a[0]), "r"(a[1]), "r"(a[2]), "r"(a[3]), "r"(b[0]), "r"(b[1]));
}

// ---------------------------------------------------------------------------
// prep kernels
// ---------------------------------------------------------------------------
__global__ void build_kvin_split2(const float* __restrict__ x, const float* __restrict__ mem,
                                  __nv_bfloat16* __restrict__ out) {
    size_t i = (size_t)blockIdx.x * blockDim.x + threadIdx.x;
    const size_t total = (size_t)BATCH * JDIM * 256;
    if (i >= total) return;
    size_t r = i >> 8;
    int c4 = (int)(i & 255) * 4;
    size_t b = r / JDIM, m = r % JDIM;
    float4 v;
    if (m < MEMLEN) v = *(const float4*)&mem[(b * MEMLEN + m) * DMODEL + c4];
    else            v = *(const float4*)&x  [(b * TLEN + (m - MEMLEN)) * DMODEL + c4];
    __nv_bfloat16 h[4], l[4];
    split1(v.x, h[0], l[0]); split1(v.y, h[1], l[1]);
    split1(v.z, h[2], l[2]); split1(v.w, h[3], l[3]);
    __nv_bfloat16* o = out + r * KP2;
    *(__nv_bfloat162*)(o + c4)              = __halves2bfloat162(h[0], h[1]);
    *(__nv_bfloat162*)(o + c4 + 2)          = __halves2bfloat162(h[2], h[3]);
    *(__nv_bfloat162*)(o + DMODEL + c4)     = __halves2bfloat162(l[0], l[1]);
    *(__nv_bfloat162*)(o + DMODEL + c4 + 2) = __halves2bfloat162(l[2], l[3]);
}

__global__ void transpose_split2(const float* __restrict__ W, __nv_bfloat16* __restrict__ T2, int N) {
    __shared__ float t[32][33];
    int k0 = blockIdx.y * 32, n0 = blockIdx.x * 32;
    int tx = threadIdx.x, ty = threadIdx.y;
#pragma unroll
    for (int i = 0; i < 32; i += 8)
        t[ty + i][tx] = W[(size_t)(k0 + ty + i) * N + n0 + tx];
    __syncthreads();
#pragma unroll
    for (int i = 0; i < 32; i += 8) {
        float v = t[tx][ty + i];
        int n = n0 + ty + i, k = k0 + tx;
        __nv_bfloat16 h, l;
        split1(v, h, l);
        __nv_bfloat16* o = T2 + (size_t)n * KP2;
        o[k] = h; o[DMODEL + k] = l;
    }
}

__global__ void build_rel2k(const float* __restrict__ rel, __nv_bfloat16* __restrict__ rel2) {
    size_t i = (size_t)blockIdx.x * blockDim.x + threadIdx.x;
    const size_t total = (size_t)JDIM * NHEAD * 16;
    if (i >= total) return;
    int c4 = (int)(i & 15) * 4;
    int h  = (int)(i >> 4) & 15;
    int u  = (int)(i >> 8);
    float4 v = *(const float4*)&rel[((size_t)u * NHEAD + h) * DHEAD + c4];
    __nv_bfloat16* o = rel2 + ((size_t)h * JDIM + u) * 64;
    *(__nv_bfloat162*)(o + c4)     = __halves2bfloat162(__float2bfloat16(v.x), __float2bfloat16(v.y));
    *(__nv_bfloat162*)(o + c4 + 2) = __halves2bfloat162(__float2bfloat16(v.z), __float2bfloat16(v.w));
}

__global__ void copy_x(const float* __restrict__ x, float* __restrict__ dst) {
    size_t i = (size_t)blockIdx.x * blockDim.x + threadIdx.x;
    const size_t total = (size_t)BATCH * TLEN * DMODEL / 4;
    if (i < total) ((float4*)dst)[i] = ((const float4*)x)[i];
}

// ---------------------------------------------------------------------------
// wmma bf16 GEMM, 128x128 tile, 3-stage cp.async, 2 CTAs/SM.
// Logical Kp=3072 ([Ah|Al|Ah] x [Bh|Bh|Bl]); physical [h|l] (stride KP2) with
// per-stage remap: A eff = k>=2048 ? k-2048 : k ; B eff = k>=1024 ? k-1024 : k.
// mode 0: C = A@B^T + bias ; mode 1: q-proj -> q2 (x0.125) ; mode 2: kv-proj.
// ---------------------------------------------------------------------------
#define STG_BYTES 20480
#define LDS_ROW   40
#define NSTAGE    3

__global__ __launch_bounds__(256, 2)
void tgemm_wmma(const __nv_bfloat16* __restrict__ A, const __nv_bfloat16* __restrict__ B,
                const float* __restrict__ bias, float* __restrict__ C,
                __nv_bfloat16* __restrict__ q2o,
                __nv_bfloat16* __restrict__ khlo, __nv_bfloat16* __restrict__ vhlo,
                int M, int N, int mode, int aremap) {
    extern __shared__ char sm[];
    const uint32_t sbase = smem_u32(sm);
    float* biasS = (float*)(sm + NSTAGE * STG_BYTES);

    const int tid = threadIdx.x;
    const int wid = tid >> 5;
    const int wm = wid >> 2;
    const int wn = wid & 3;
    const int row0 = blockIdx.y * 128;
    const int col0 = blockIdx.x * 128;

    const int arow0 = aremap ? (row0 + ((row0 >> 10) + 1) * 1024) : row0;
    const __nv_bfloat16* Ap = A + (size_t)arow0 * KP2;

    if (mode == 0)
        for (int i = tid; i < 16 * 128; i += 256)
            biasS[i] = bias ? bias[col0 + (i & 127)] : 0.f;

    auto loadStage = [&](int s, int k0) {
        const int ka = (k0 >= 2048) ? k0 - 2048 : k0;   // A slab remap
        const int kb = (k0 >= 1024) ? k0 - 1024 : k0;   // B slab remap
        uint32_t ab = sbase + s * STG_BYTES;
        uint32_t bb = ab + STG_BYTES / 2;
#pragma unroll
        for (int p = 0; p < 2; ++p) {
            int i = tid + p * 256;
            int r = i >> 2, qq = i & 3;
            cpasync16s(ab + r * 80 + qq * 16,
                       (const char*)Ap + (((size_t)r) * KP2 + ka + qq * 8) * 2);
            cpasync16s(bb + r * 80 + qq * 16,
                       (const char*)B + (((size_t)(col0 + r)) * KP2 + kb + qq * 8) * 2);
        }
    };

    wmma::fragment<wmma::accumulator, 16, 16, 16, float> acc[4][2];
    __syncthreads();
    if (mode == 0) {
#pragma unroll
        for (int i = 0; i < 4; ++i)
#pragma unroll
            for (int j = 0; j < 2; ++j)
                wmma::load_matrix_sync(acc[i][j], &biasS[wn * 32 + j * 16], 128, wmma::mem_row_major);
    } else {
#pragma unroll
        for (int i = 0; i < 4; ++i)
#pragma unroll
            for (int j = 0; j < 2; ++j)
                wmma::fill_fragment(acc[i][j], 0.f);
    }

    loadStage(0, 0); cp_commit();
    loadStage(1, 32); cp_commit();

    const int nst = KP3 / 32;
    for (int st = 0; st < nst; ++st) {
        if (st == nst - 1) cp_wait0(); else cp_wait1();
        __syncthreads();
        if (st + 2 < nst) { loadStage((st + 2) % NSTAGE, (st + 2) * 32); cp_commit(); }

        const __nv_bfloat16* as = (const __nv_bfloat16*)(sm + (st % NSTAGE) * STG_BYTES);
        const __nv_bfloat16* bs = as + STG_BYTES / 4;

#pragma unroll
        for (int kk = 0; kk < 2; ++kk) {
            wmma::fragment<wmma::matrix_a, 16, 16, 16, __nv_bfloat16, wmma::row_major> af[4];
            wmma::fragment<wmma::matrix_b, 16, 16, 16, __nv_bfloat16, wmma::col_major> bfr[2];
#pragma unroll
            for (int i = 0; i < 4; ++i)
                wmma::load_matrix_sync(af[i], as + (wm * 64 + i * 16) * LDS_ROW + kk * 16, LDS_ROW);
#pragma unroll
            for (int j = 0; j < 2; ++j)
                wmma::load_matrix_sync(bfr[j], bs + (wn * 32 + j * 16) * LDS_ROW + kk * 16, LDS_ROW);
#pragma unroll
            for (int i = 0; i < 4; ++i)
#pragma unroll
                for (int j = 0; j < 2; ++j)
                    wmma::mma_sync(acc[i][j], af[i], bfr[j], acc[i][j]);
        }
    }

    if (mode == 0) {
#pragma unroll
        for (int i = 0; i < 4; ++i)
#pragma unroll
            for (int j = 0; j < 2; ++j)
                wmma::store_matrix_sync(&C[(size_t)(row0 + wm * 64 + i * 16) * N + col0 + wn * 32 + j * 16],
                                        acc[i][j], N, wmma::mem_row_major);
        return;
    }

    __syncthreads();
    float* Cs = (float*)sm;   // [128][132]
#pragma unroll
    for (int i = 0; i < 4; ++i)
#pragma unroll
        for (int j = 0; j < 2; ++j)
            wmma::store_matrix_sync(&Cs[(size_t)(wm * 64 + i * 16) * 132 + wn * 32 + j * 16],
                                    acc[i][j], 132, wmma::mem_row_major);
    __syncthreads();

    if (mode == 1) {
        for (int idx = tid; idx < 128 * 64; idx += 256) {
            int r = idx >> 6, c2 = (idx & 63) * 2;
            float v0 = Cs[r * 132 + c2] * 0.125f, v1 = Cs[r * 132 + c2 + 1] * 0.125f;
            __nv_bfloat16 h0, l0, h1, l1;
            split1(v0, h0, l0); split1(v1, h1, l1);
            int bt = row0 + r, gc = col0 + c2;
            int b = bt >> 10, t = bt & 1023;
            int h = gc >> 6, cc = gc & 63;
            __nv_bfloat16* o = q2o + (((size_t)(b * NHEAD + h) * TLEN + t)) * 128 + cc;
            *(__nv_bfloat162*)(o)      = __halves2bfloat162(h0, h1);
            *(__nv_bfloat162*)(o + 64) = __halves2bfloat162(l0, l1);
        }
    } else {
        for (int idx = tid; idx < 128 * 64; idx += 256) {
            int r = idx >> 6, c2 = (idx & 63) * 2;
            float v0 = Cs[r * 132 + c2], v1 = Cs[r * 132 + c2 + 1];
            __nv_bfloat16 h0, l0, h1, l1;
            split1(v0, h0, l0); split1(v1, h1, l1);
            int rg = row0 + r, gc = col0 + c2;
            int b = rg >> 11, m = rg & 2047;
            __nv_bfloat16* dst = (gc < DMODEL) ? khlo : vhlo;
            int gcl = (gc < DMODEL) ? gc : gc - DMODEL;
            int h = gcl >> 6, cc = gcl & 63;
            __nv_bfloat16* o = dst + (((size_t)(b * NHEAD + h) * JDIM + m)) * 128 + cc;
            *(__nv_bfloat162*)(o)      = __halves2bfloat162(h0, h1);
            *(__nv_bfloat162*)(o + 64) = __halves2bfloat162(l0, l1);
        }
    }
}

// ---------------------------------------------------------------------------
// FA2-style flash attention (round-14 design; scale folded into q2)
// ---------------------------------------------------------------------------
struct __align__(16) AttnW {
    __nv_bfloat16 Q2s[128][136];      // [Qh(64) | Ql(64)]  (x0.125)
    __nv_bfloat16 Khl[2][64][136];    // [Kh | Kl]
    __nv_bfloat16 Vhl[2][64][136];    // [Vh | Vl]
    __nv_bfloat16 Wh[4][64][72];      // W span ring (hi only), slot = (u>>6)&3
    __nv_bfloat16 Rx[3][128][72];     // rel scores ring, slot = (u>>6)%3
};

__device__ __forceinline__ void aw_pf_K(AttnW& S, int bb, const __nv_bfloat16* __restrict__ khl,
                                        size_t bh, int m0, int tid) {
#pragma unroll
    for (int p = 0; p < 4; ++p) {
        int i = tid + p * 256;
        int r = i >> 4, c = i & 15;
        cpasync16(&S.Khl[bb][r][c * 8], khl + (bh * JDIM + (size_t)(m0 + r)) * 128 + c * 8);
    }
}
__device__ __forceinline__ void aw_pf_V(AttnW& S, int bb, const __nv_bfloat16* __restrict__ vhl,
                                        size_t bh, int m0, int tid) {
#pragma unroll
    for (int p = 0; p < 4; ++p) {
        int i = tid + p * 256;
        int r = i >> 4, c = i & 15;
        cpasync16(&S.Vhl[bb][r][c * 8], vhl + (bh * JDIM + (size_t)(m0 + r)) * 128 + c * 8);
    }
}
__device__ __forceinline__ void aw_pf_W(AttnW& S, const __nv_bfloat16* __restrict__ rel2,
                                        int h, int ub, int tid) {
    int slot = (ub >> 6) & 3;
#pragma unroll
    for (int p = 0; p < 2; ++p) {
        int i = tid + p * 256;
        int o = i >> 3, c = i & 7;
        int u = ub + o; if (u > JDIM - 1) u = JDIM - 1;
        cpasync16(&S.Wh[slot][o][c * 8], rel2 + ((size_t)h * JDIM + u) * 64 + c * 8);
    }
}

__global__ __launch_bounds__(256, 1)
void attn_mma(const __nv_bfloat16* __restrict__ q2,
              const __nv_bfloat16* __restrict__ khl,
              const __nv_bfloat16* __restrict__ vhl,
              const __nv_bfloat16* __restrict__ rel2,
              __nv_bfloat16* __restrict__ a2) {
    extern __shared__ char smem_raw[];
    AttnW& S = *reinterpret_cast<AttnW*>(smem_raw);

    const int b  = blockIdx.z;
    const int h  = blockIdx.y;
    const int rb = (int)gridDim.x - 1 - (int)blockIdx.x;   // long blocks first
    const int r0 = rb * 128;
    const size_t bh = (size_t)(b * NHEAD + h);
    const int tid = threadIdx.x;
    const int wid = tid >> 5;
    const int lane = tid & 31;
    const int g   = lane >> 2;
    const int tig = lane & 3;
    const int rowbase = wid * 16;
    const int rl1 = rowbase + g;
    const int rl2 = rl1 + 8;

#pragma unroll
    for (int p = 0; p < 8; ++p) {
        int i = tid + p * 256;
        int r = i >> 4, c = i & 15;
        cpasync16(&S.Q2s[r][c * 8],
                  q2 + (bh * TLEN + (size_t)(r0 + r)) * 128 + c * 8);
    }
    aw_pf_K(S, 0, khl, bh, 0, tid);
    aw_pf_V(S, 0, vhl, bh, 0, tid);
    const int ubase0 = 896 - r0;
    aw_pf_W(S, rel2, h, ubase0,        tid);
    aw_pf_W(S, rel2, h, ubase0 + 64,   tid);
    aw_pf_W(S, rel2, h, ubase0 + 128,  tid);
    cp_commit();

    float accf[8][4];
#pragma unroll
    for (int i = 0; i < 8; ++i)
#pragma unroll
        for (int j = 0; j < 4; ++j) accf[i][j] = 0.f;
    float mreg[2] = {-1e30f, -1e30f};
    float lreg[2] = {0.f, 0.f};

    uint32_t aQh[4][4], aQl[4][4];

    const int ntiles = min(32, 2 * rb + 18);

    for (int mt = 0; mt < ntiles; ++mt) {
        const int cur = mt & 1;
        const int prv = cur ^ 1;
        const int m0  = mt * 64;

        cp_wait0();
        __syncthreads();

        if (mt == 0) {
            int s = lane >> 3, rr2 = lane & 7;
            int arow = rowbase + (s & 1) * 8 + rr2;
            int acol = (s >> 1) * 8;
#pragma unroll
            for (int k16 = 0; k16 < 4; ++k16) {
                ldmx4(aQh[k16], smem_u32(&S.Q2s[arow][acol + k16 * 16]));
                ldmx4(aQl[k16], smem_u32(&S.Q2s[arow][64 + acol + k16 * 16]));
            }
        }

        if (mt + 1 < ntiles) {
            aw_pf_K(S, prv, khl, bh, m0 + 64, tid);
            aw_pf_V(S, prv, vhl, bh, m0 + 64, tid);
            cp_commit();
        }

        // ---- R: compute new slot(s) = Qh @ Wh^T for warp's 16 rows ----
        {
            const int nR = (mt == 0) ? 3 : 1;
#pragma unroll
            for (int rr = 0; rr < nR; ++rr) {
                int ub = (mt == 0) ? (ubase0 + 64 * rr) : (ubase0 + 64 * (mt + 2));
                int wslot = (ub >> 6) & 3;
                int rslot = (ub >> 6) % 3;
#pragma unroll
                for (int nt = 0; nt < 8; ++nt) {
                    float c[4] = {0.f, 0.f, 0.f, 0.f};
#pragma unroll
                    for (int k16 = 0; k16 < 4; ++k16) {
                        uint32_t bw[2];
                        ldmx2(bw, smem_u32(&S.Wh[wslot][nt * 8 + (lane & 7)]
                                                 [k16 * 16 + 8 * ((lane >> 3) & 1)]));
                        mma16816(c, aQh[k16], bw);
                    }
                    int colc = 8 * nt + 2 * tig;
                    *(__nv_bfloat162*)&S.Rx[rslot][rl1][colc] =
                        __halves2bfloat162(__float2bfloat16(c[0]), __float2bfloat16(c[1]));
                    *(__nv_bfloat162*)&S.Rx[rslot][rl2][colc] =
                        __halves2bfloat162(__float2bfloat16(c[2]), __float2bfloat16(c[3]));
                }
            }
        }
        __syncwarp();

        // ---- S: 3 compensated passes into register fragments ----
        float sc[8][4];
#pragma unroll
        for (int nt = 0; nt < 8; ++nt) {
#pragma unroll
            for (int j = 0; j < 4; ++j) sc[nt][j] = 0.f;
#pragma unroll
            for (int k16 = 0; k16 < 4; ++k16) {
                uint32_t bkh[2], bkl[2];
                int krow = nt * 8 + (lane & 7);
                int kc = k16 * 16 + 8 * ((lane >> 3) & 1);
                ldmx2(bkh, smem_u32(&S.Khl[cur][krow][kc]));
                ldmx2(bkl, smem_u32(&S.Khl[cur][krow][64 + kc]));
                mma16816(sc[nt], aQh[k16], bkh);
                mma16816(sc[nt], aQl[k16], bkh);
                mma16816(sc[nt], aQh[k16], bkl);
            }
        }

        // ---- softmax in registers (rows rl1, rl2; quad reduction) ----
        uint32_t phx[2][8], plx[2][8];
        float alpha[2];
#pragma unroll
        for (int ri = 0; ri < 2; ++ri) {
            const int rl = (ri == 0) ? rl1 : rl2;
            const int mlim = r0 + rl + MEMLEN - m0;
            const int ubase = m0 + 1023 - r0 - rl;
            float sv[8][2];
            float rmax = -1e30f;
#pragma unroll
            for (int nt = 0; nt < 8; ++nt) {
#pragma unroll
                for (int j = 0; j < 2; ++j) {
                    int mm = 8 * nt + 2 * tig + j;
                    int u = ubase + mm;
                    int slot = (u >> 6) % 3;
                    float rv = __bfloat162float(S.Rx[slot][rl][u & 63]);
                    float s = sc[nt][2 * ri + j] + rv;
                    if (mm > mlim) s = -1e30f;
                    sv[nt][j] = s;
                    rmax = fmaxf(rmax, s);
                }
            }
            rmax = fmaxf(rmax, __shfl_xor_sync(0xffffffffu, rmax, 1));
            rmax = fmaxf(rmax, __shfl_xor_sync(0xffffffffu, rmax, 2));
            float mnew = fmaxf(mreg[ri], rmax);
            alpha[ri] = __expf(mreg[ri] - mnew);
            float lsum = 0.f;
#pragma unroll
            for (int nt = 0; nt < 8; ++nt) {
                float p0 = __expf(sv[nt][0] - mnew);
                float p1 = __expf(sv[nt][1] - mnew);
                lsum += p0 + p1;
                __nv_bfloat16 h0 = __float2bfloat16(p0);
                __nv_bfloat16 h1 = __float2bfloat16(p1);
                phx[ri][nt] = packbf2(h0, h1);
                plx[ri][nt] = packbf2(__float2bfloat16(p0 - __bfloat162float(h0)),
                                      __float2bfloat16(p1 - __bfloat162float(h1)));
            }
            lsum += __shfl_xor_sync(0xffffffffu, lsum, 1);
            lsum += __shfl_xor_sync(0xffffffffu, lsum, 2);
            lreg[ri] = lreg[ri] * alpha[ri] + lsum;
            mreg[ri] = mnew;
        }

        // ---- PV: rescale accf, repack P C->A fragments, mma with V ----
#pragma unroll
        for (int nt = 0; nt < 8; ++nt) {
            accf[nt][0] *= alpha[0]; accf[nt][1] *= alpha[0];
            accf[nt][2] *= alpha[1]; accf[nt][3] *= alpha[1];
        }
        uint32_t aPh[4][4], aPl[4][4];
#pragma unroll
        for (int kk = 0; kk < 4; ++kk) {
            aPh[kk][0] = phx[0][2 * kk];     aPh[kk][1] = phx[1][2 * kk];
            aPh[kk][2] = phx[0][2 * kk + 1]; aPh[kk][3] = phx[1][2 * kk + 1];
            aPl[kk][0] = plx[0][2 * kk];     aPl[kk][1] = plx[1][2 * kk];
            aPl[kk][2] = plx[0][2 * kk + 1]; aPl[kk][3] = plx[1][2 * kk + 1];
        }
        {
            int s = (lane >> 3) & 1, rr2 = lane & 7;
#pragma unroll
            for (int k16 = 0; k16 < 4; ++k16) {
                int vrow = k16 * 16 + s * 8 + rr2;
#pragma unroll
                for (int nt = 0; nt < 8; ++nt) {
                    uint32_t bhv[2], blv[2];
                    ldmx2t(bhv, smem_u32(&S.Vhl[cur][vrow][nt * 8]));
                    ldmx2t(blv, smem_u32(&S.Vhl[cur][vrow][64 + nt * 8]));
                    mma16816(accf[nt], aPh[k16], bhv);
                    mma16816(accf[nt], aPl[k16], bhv);
                    mma16816(accf[nt], aPh[k16], blv);
                }
            }
        }

        if (mt + 1 < ntiles) {
            aw_pf_W(S, rel2, h, ubase0 + 64 * (mt + 3), tid);
            cp_commit();
        }
    }

    // ---- epilogue: write a2 [row][2048] = [h | l] from fragments ----
    {
        float inv1 = 1.f / lreg[0];
        float inv2 = 1.f / lreg[1];
        size_t grow1 = (size_t)(b * TLEN + r0 + rl1) * KP2;
        size_t grow2 = (size_t)(b * TLEN + r0 + rl2) * KP2;
#pragma unroll
        for (int nt = 0; nt < 8; ++nt) {
            int col = h * 64 + 8 * nt + 2 * tig;
            float v0 = accf[nt][0] * inv1, v1 = accf[nt][1] * inv1;
            float v2 = accf[nt][2] * inv2, v3 = accf[nt][3] * inv2;
            __nv_bfloat16 h0, l0, h1, l1, h2, l2, h3, l3;
            split1(v0, h0, l0); split1(v1, h1, l1);
            split1(v2, h2, l2); split1(v3, h3, l3);
            __nv_bfloat16* o1 = a2 + grow1 + col;
            __nv_bfloat16* o2 = a2 + grow2 + col;
            *(__nv_bfloat162*)(o1)          = __halves2bfloat162(h0, h1);
            *(__nv_bfloat162*)(o1 + DMODEL) = __halves2bfloat162(l0, l1);
            *(__nv_bfloat162*)(o2)          = __halves2bfloat162(h2, h3);
            *(__nv_bfloat162*)(o2 + DMODEL) = __halves2bfloat162(l2, l3);
        }
    }
}

// ---------------------------------------------------------------------------
extern "C" void kernel_launch(void* const* d_in, const int* in_sizes, int n_in,
                              void* d_out, int out_size) {
    const float* x    = (const float*)d_in[0];
    const float* mem  = (const float*)d_in[1];
    const float* wq   = (const float*)d_in[2];
    const float* wkv  = (const float*)d_in[3];
    const float* wo   = (const float*)d_in[4];
    const float* bo   = (const float*)d_in[5];
    const float* relw = (const float*)d_in[6];

    float* out_main = (float*)d_out;
    float* mem_next = out_main + (size_t)BATCH * TLEN * DMODEL;

    __nv_bfloat16 *kvin2, *a2, *wq2, *wkv2, *wo2, *q2, *rel2, *khl, *vhl;
    cudaGetSymbolAddress((void**)&kvin2, g_kvin2);
    cudaGetSymbolAddress((void**)&a2,    g_a2);
    cudaGetSymbolAddress((void**)&wq2,   g_wq2);
    cudaGetSymbolAddress((void**)&wkv2,  g_wkv2);
    cudaGetSymbolAddress((void**)&wo2,   g_wo2);
    cudaGetSymbolAddress((void**)&q2,    g_q2);
    cudaGetSymbolAddress((void**)&rel2,  g_rel2);
    cudaGetSymbolAddress((void**)&khl,   g_khl);
    cudaGetSymbolAddress((void**)&vhl,   g_vhl);

    const int TG_SMEM = NSTAGE * STG_BYTES + 16 * 128 * 4;    // 69632
    const int AW_SMEM = (int)sizeof(AttnW);
    cudaFuncSetAttribute(tgemm_wmma, cudaFuncAttributeMaxDynamicSharedMemorySize, TG_SMEM);
    cudaFuncSetAttribute(attn_mma,   cudaFuncAttributeMaxDynamicSharedMemorySize, AW_SMEM);

    // operand prep
    {
        size_t tot = (size_t)BATCH * JDIM * 256;
        build_kvin_split2<<<(unsigned)((tot + 255) / 256), 256>>>(x, mem, kvin2);
    }
    transpose_split2<<<dim3(DMODEL / 32, DMODEL / 32), dim3(32, 8)>>>(wq, wq2, DMODEL);
    transpose_split2<<<dim3(2 * DMODEL / 32, DMODEL / 32), dim3(32, 8)>>>(wkv, wkv2, 2 * DMODEL);
    transpose_split2<<<dim3(DMODEL / 32, DMODEL / 32), dim3(32, 8)>>>(wo, wo2, DMODEL);
    {
        size_t tot = (size_t)JDIM * NHEAD * 16;
        build_rel2k<<<(unsigned)((tot + 255) / 256), 256>>>(relw, rel2);
    }

    // q-proj -> q2 (mode 1); A = x rows inside kvin2 (aremap)
    tgemm_wmma<<<dim3(DMODEL / 128, BATCH * TLEN / 128), 256, TG_SMEM>>>(
        kvin2, wq2, nullptr, nullptr, q2, nullptr, nullptr, BATCH * TLEN, DMODEL, 1, 1);
    // kv-proj -> khl/vhl (mode 2)
    tgemm_wmma<<<dim3(2 * DMODEL / 128, BATCH * JDIM / 128), 256, TG_SMEM>>>(
        kvin2, wkv2, nullptr, nullptr, nullptr, khl, vhl, BATCH * JDIM, 2 * DMODEL, 2, 0);
    // flash attention -> a2 (128 q-rows per block)
    attn_mma<<<dim3(TLEN / 128, NHEAD, BATCH), 256, AW_SMEM>>>(q2, khl, vhl, rel2, a2);
    // out = attn @ wo + bo (mode 0)
    tgemm_wmma<<<dim3(DMODEL / 128, BATCH * TLEN / 128), 256, TG_SMEM>>>(
        a2, wo2, bo, out_main, nullptr, nullptr, nullptr, BATCH * TLEN, DMODEL, 0, 0);
    // mem_next = x
    {
        size_t n4 = (size_t)BATCH * TLEN * DMODEL / 4;
        copy_x<<<(unsigned)((n4 + 255) / 256), 256>>>(x, mem_next);
    }
}

// round 17
// speedup vs baseline: 1.3914x; 1.0831x over previous
#include <cuda_runtime.h>
#include <cuda_bf16.h>
#include <mma.h>
#include <cstddef>
#include <cstdint>

using namespace nvcuda;

#define BATCH   4
#define TLEN    1024
#define MEMLEN  1024
#define JDIM    2048
#define DMODEL  1024
#define NHEAD   16
#define DHEAD   64
#define KP2     2048      // physical storage: [h | l]

// -------- scratch (static __device__ globals; cudaMalloc is forbidden) ------
__device__ __nv_bfloat16 g_kvin2[(size_t)BATCH * JDIM * KP2];    // [h|l]
__device__ __nv_bfloat16 g_a2   [(size_t)BATCH * TLEN * KP2];    // [h|l]
__device__ __nv_bfloat16 g_wq2  [(size_t)DMODEL * KP2];          // [h|l] (transposed)
__device__ __nv_bfloat16 g_wkv2 [(size_t)2 * DMODEL * KP2];      // [h|l]
__device__ __nv_bfloat16 g_wo2  [(size_t)DMODEL * KP2];          // [h|l]
__device__ __nv_bfloat16 g_q2   [(size_t)BATCH * NHEAD * TLEN * 128];  // [Qh|Ql] (x0.125)
__device__ __nv_bfloat16 g_rel2 [(size_t)NHEAD * JDIM * 64];           // hi only
__device__ __nv_bfloat16 g_khl  [(size_t)BATCH * NHEAD * JDIM * 128];  // [Kh|Kl]
__device__ __nv_bfloat16 g_vhl  [(size_t)BATCH * NHEAD * JDIM * 128];  // [Vh|Vl]

// ---------------------------------------------------------------------------
__device__ __forceinline__ uint32_t smem_u32(const void* p) {
    uint32_t a;
    asm("{ .reg .u64 t; cvta.to.shared.u64 t, %1; cvt.u32.u64 %0, t; }" : "=r"(a) : "l"(p));
    return a;
}
__device__ __forceinline__ void cpasync16s(uint32_t saddr, const void* gsrc) {
    asm volatile("cp.async.cg.shared.global [%0], [%1], 16;\n" :: "r"(saddr), "l"(gsrc));
}
__device__ __forceinline__ void cpasync16(void* smem_dst, const void* gsrc) {
    cpasync16s((uint32_t)__cvta_generic_to_shared(smem_dst), gsrc);
}
__device__ __forceinline__ void cp_commit() { asm volatile("cp.async.commit_group;\n"); }
__device__ __forceinline__ void cp_wait0()  { asm volatile("cp.async.wait_group 0;\n"); }

__device__ __forceinline__ void split1(float v, __nv_bfloat16& h, __nv_bfloat16& l) {
    h = __float2bfloat16(v);
    l = __float2bfloat16(v - __bfloat162float(h));
}
__device__ __forceinline__ uint32_t packbf2(__nv_bfloat16 lo, __nv_bfloat16 hi) {
    return (uint32_t)__bfloat16_as_ushort(lo) | ((uint32_t)__bfloat16_as_ushort(hi) << 16);
}

// raw tensor-core primitives (documented PTX layouts, sm_80+)
__device__ __forceinline__ void ldmx4(uint32_t* r, uint32_t addr) {
    asm volatile("ldmatrix.sync.aligned.m8n8.x4.shared.b16 {%0,%1,%2,%3}, [%4];"
                 : "=r"(r[0]), "=r"(r[1]), "=r"(r[2]), "=r"(r[3]) : "r"(addr));
}
__device__ __forceinline__ void ldmx2(uint32_t* r, uint32_t addr) {
    asm volatile("ldmatrix.sync.aligned.m8n8.x2.shared.b16 {%0,%1}, [%2];"
                 : "=r"(r[0]), "=r"(r[1]) : "r"(addr));
}
__device__ __forceinline__ void ldmx2t(uint32_t* r, uint32_t addr) {
    asm volatile("ldmatrix.sync.aligned.m8n8.x2.trans.shared.b16 {%0,%1}, [%2];"
                 : "=r"(r[0]), "=r"(r[1]) : "r"(addr));
}
__device__ __forceinline__ void mma16816(float* c, const uint32_t* a, const uint32_t* b) {
    asm volatile("mma.sync.aligned.m16n8k16.row.col.f32.bf16.bf16.f32 "
                 "{%0,%1,%2,%3},{%4,%5,%6,%7},{%8,%9},{%0,%1,%2,%3};"
                 : "+f"(c[0]), "+f"(c[1]), "+f"(c[2]), "+f"(c[3])
                 : "r"(a[0]), "r"(a[1]), "r"(a[2]), "r"(a[3]), "r"(b[0]), "r"(b[1]));
}

// ---------------------------------------------------------------------------
// prep kernels
// ---------------------------------------------------------------------------
// kvin (bf16 split) + mem_next (= x, fp32) in one pass
__global__ void build_kvin_split2(const float* __restrict__ x, const float* __restrict__ mem,
                                  __nv_bfloat16* __restrict__ out, float* __restrict__ mem_next) {
    size_t i = (size_t)blockIdx.x * blockDim.x + threadIdx.x;
    const size_t total = (size_t)BATCH * JDIM * 256;
    if (i >= total) return;
    size_t r = i >> 8;
    int c4 = (int)(i & 255) * 4;
    size_t b = r / JDIM, m = r % JDIM;
    float4 v;
    if (m < MEMLEN) {
        v = *(const float4*)&mem[(b * MEMLEN + m) * DMODEL + c4];
    } else {
        v = *(const float4*)&x[(b * TLEN + (m - MEMLEN)) * DMODEL + c4];
        *(float4*)&mem_next[(b * TLEN + (m - MEMLEN)) * DMODEL + c4] = v;
    }
    __nv_bfloat16 h[4], l[4];
    split1(v.x, h[0], l[0]); split1(v.y, h[1], l[1]);
    split1(v.z, h[2], l[2]); split1(v.w, h[3], l[3]);
    __nv_bfloat16* o = out + r * KP2;
    *(__nv_bfloat162*)(o + c4)              = __halves2bfloat162(h[0], h[1]);
    *(__nv_bfloat162*)(o + c4 + 2)          = __halves2bfloat162(h[2], h[3]);
    *(__nv_bfloat162*)(o + DMODEL + c4)     = __halves2bfloat162(l[0], l[1]);
    *(__nv_bfloat162*)(o + DMODEL + c4 + 2) = __halves2bfloat162(l[2], l[3]);
}

// all three weight transposes in one launch; z selects target
__global__ void transpose_split2_all(const float* __restrict__ wq, const float* __restrict__ wkv,
                                     const float* __restrict__ wo,
                                     __nv_bfloat16* __restrict__ wq2,
                                     __nv_bfloat16* __restrict__ wkv2,
                                     __nv_bfloat16* __restrict__ wo2) {
    __shared__ float t[32][33];
    const int z = blockIdx.z;
    const float* W; __nv_bfloat16* T; int N; int coff;
    if (z == 0)      { W = wq;  T = wq2;  N = DMODEL;     coff = 0; }
    else if (z == 3) { W = wo;  T = wo2;  N = DMODEL;     coff = 0; }
    else             { W = wkv; T = wkv2; N = 2 * DMODEL; coff = (z - 1) * DMODEL; }
    int k0 = blockIdx.y * 32, n0 = blockIdx.x * 32 + coff;
    int tx = threadIdx.x, ty = threadIdx.y;
#pragma unroll
    for (int i = 0; i < 32; i += 8)
        t[ty + i][tx] = W[(size_t)(k0 + ty + i) * N + n0 + tx];
    __syncthreads();
#pragma unroll
    for (int i = 0; i < 32; i += 8) {
        float v = t[tx][ty + i];
        int n = n0 + ty + i, k = k0 + tx;
        __nv_bfloat16 h, l;
        split1(v, h, l);
        __nv_bfloat16* o = T + (size_t)n * KP2;
        o[k] = h; o[DMODEL + k] = l;
    }
}

__global__ void build_rel2k(const float* __restrict__ rel, __nv_bfloat16* __restrict__ rel2) {
    size_t i = (size_t)blockIdx.x * blockDim.x + threadIdx.x;
    const size_t total = (size_t)JDIM * NHEAD * 16;
    if (i >= total) return;
    int c4 = (int)(i & 15) * 4;
    int h  = (int)(i >> 4) & 15;
    int u  = (int)(i >> 8);
    float4 v = *(const float4*)&rel[((size_t)u * NHEAD + h) * DHEAD + c4];
    __nv_bfloat16* o = rel2 + ((size_t)h * JDIM + u) * 64;
    *(__nv_bfloat162*)(o + c4)     = __halves2bfloat162(__float2bfloat16(v.x), __float2bfloat16(v.y));
    *(__nv_bfloat162*)(o + c4 + 2) = __halves2bfloat162(__float2bfloat16(v.z), __float2bfloat16(v.w));
}

// ---------------------------------------------------------------------------
// Fused-window compensated GEMM: 128x128 tile, 32 K-windows of 32 cols.
// Per window load {Ah, Al, Bh, Bl} (4 slabs) once, run 3 mma passes:
//   C += Ah*Bh + Al*Bh + Ah*Bl.  Double-buffered, 2 CTAs/SM.
// mode 0: C = A@B^T + bias ; mode 1: q-proj -> q2 (x0.125) ; mode 2: kv-proj.
// ---------------------------------------------------------------------------
#define SLAB      10240               // 128 rows x 80 B
#define STG4      (4 * SLAB)          // 40960
#define LDS_ROW   40

__global__ __launch_bounds__(256, 2)
void tgemm_wmma(const __nv_bfloat16* __restrict__ A, const __nv_bfloat16* __restrict__ B,
                const float* __restrict__ bias, float* __restrict__ C,
                __nv_bfloat16* __restrict__ q2o,
                __nv_bfloat16* __restrict__ khlo, __nv_bfloat16* __restrict__ vhlo,
                int M, int N, int mode, int aremap) {
    extern __shared__ char sm[];
    const uint32_t sbase = smem_u32(sm);
    float* biasS = (float*)(sm + 2 * STG4);

    const int tid = threadIdx.x;
    const int wid = tid >> 5;
    const int wm = wid >> 2;
    const int wn = wid & 3;
    const int row0 = blockIdx.y * 128;
    const int col0 = blockIdx.x * 128;

    const int arow0 = aremap ? (row0 + ((row0 >> 10) + 1) * 1024) : row0;
    const __nv_bfloat16* Ap = A + (size_t)arow0 * KP2;

    if (mode == 0)
        for (int i = tid; i < 16 * 128; i += 256)
            biasS[i] = bias ? bias[col0 + (i & 127)] : 0.f;

    // load one 32-col window: Ah, Al, Bh, Bl slabs
    auto loadStage = [&](int s, int k0) {
        uint32_t base = sbase + s * STG4;
#pragma unroll
        for (int p = 0; p < 2; ++p) {
            int i = tid + p * 256;
            int r = i >> 2, qq = i & 3;
            size_t arow = (size_t)r * KP2;
            cpasync16s(base + r * 80 + qq * 16,                      // Ah
                       (const char*)Ap + (arow + k0 + qq * 8) * 2);
            cpasync16s(base + SLAB + r * 80 + qq * 16,               // Al
                       (const char*)Ap + (arow + DMODEL + k0 + qq * 8) * 2);
            size_t brow = (size_t)(col0 + r) * KP2;
            cpasync16s(base + 2 * SLAB + r * 80 + qq * 16,           // Bh
                       (const char*)B + (brow + k0 + qq * 8) * 2);
            cpasync16s(base + 3 * SLAB + r * 80 + qq * 16,           // Bl
                       (const char*)B + (brow + DMODEL + k0 + qq * 8) * 2);
        }
    };

    wmma::fragment<wmma::accumulator, 16, 16, 16, float> acc[4][2];
    __syncthreads();
    if (mode == 0) {
#pragma unroll
        for (int i = 0; i < 4; ++i)
#pragma unroll
            for (int j = 0; j < 2; ++j)
                wmma::load_matrix_sync(acc[i][j], &biasS[wn * 32 + j * 16], 128, wmma::mem_row_major);
    } else {
#pragma unroll
        for (int i = 0; i < 4; ++i)
#pragma unroll
            for (int j = 0; j < 2; ++j)
                wmma::fill_fragment(acc[i][j], 0.f);
    }

    loadStage(0, 0); cp_commit();

    const int nst = DMODEL / 32;   // 32 windows
    for (int st = 0; st < nst; ++st) {
        cp_wait0();
        __syncthreads();
        if (st + 1 < nst) { loadStage((st + 1) & 1, (st + 1) * 32); cp_commit(); }

        const __nv_bfloat16* base = (const __nv_bfloat16*)(sm + (st & 1) * STG4);
        const __nv_bfloat16* Ah = base;
        const __nv_bfloat16* Al = base + SLAB / 2;
        const __nv_bfloat16* Bh = base + SLAB;
        const __nv_bfloat16* Bl = base + 3 * SLAB / 2;

#pragma unroll
        for (int pass = 0; pass < 3; ++pass) {
            const __nv_bfloat16* ap = (pass == 1) ? Al : Ah;
            const __nv_bfloat16* bp = (pass == 2) ? Bl : Bh;
#pragma unroll
            for (int kk = 0; kk < 2; ++kk) {
                wmma::fragment<wmma::matrix_a, 16, 16, 16, __nv_bfloat16, wmma::row_major> af[4];
                wmma::fragment<wmma::matrix_b, 16, 16, 16, __nv_bfloat16, wmma::col_major> bfr[2];
#pragma unroll
                for (int i = 0; i < 4; ++i)
                    wmma::load_matrix_sync(af[i], ap + (wm * 64 + i * 16) * LDS_ROW + kk * 16, LDS_ROW);
#pragma unroll
                for (int j = 0; j < 2; ++j)
                    wmma::load_matrix_sync(bfr[j], bp + (wn * 32 + j * 16) * LDS_ROW + kk * 16, LDS_ROW);
#pragma unroll
                for (int i = 0; i < 4; ++i)
#pragma unroll
                    for (int j = 0; j < 2; ++j)
                        wmma::mma_sync(acc[i][j], af[i], bfr[j], acc[i][j]);
            }
        }
    }

    if (mode == 0) {
#pragma unroll
        for (int i = 0; i < 4; ++i)
#pragma unroll
            for (int j = 0; j < 2; ++j)
                wmma::store_matrix_sync(&C[(size_t)(row0 + wm * 64 + i * 16) * N + col0 + wn * 32 + j * 16],
                                        acc[i][j], N, wmma::mem_row_major);
        return;
    }

    __syncthreads();
    float* Cs = (float*)sm;   // [128][132]
#pragma unroll
    for (int i = 0; i < 4; ++i)
#pragma unroll
        for (int j = 0; j < 2; ++j)
            wmma::store_matrix_sync(&Cs[(size_t)(wm * 64 + i * 16) * 132 + wn * 32 + j * 16],
                                    acc[i][j], 132, wmma::mem_row_major);
    __syncthreads();

    if (mode == 1) {
        for (int idx = tid; idx < 128 * 64; idx += 256) {
            int r = idx >> 6, c2 = (idx & 63) * 2;
            float v0 = Cs[r * 132 + c2] * 0.125f, v1 = Cs[r * 132 + c2 + 1] * 0.125f;
            __nv_bfloat16 h0, l0, h1, l1;
            split1(v0, h0, l0); split1(v1, h1, l1);
            int bt = row0 + r, gc = col0 + c2;
            int b = bt >> 10, t = bt & 1023;
            int h = gc >> 6, cc = gc & 63;
            __nv_bfloat16* o = q2o + (((size_t)(b * NHEAD + h) * TLEN + t)) * 128 + cc;
            *(__nv_bfloat162*)(o)      = __halves2bfloat162(h0, h1);
            *(__nv_bfloat162*)(o + 64) = __halves2bfloat162(l0, l1);
        }
    } else {
        for (int idx = tid; idx < 128 * 64; idx += 256) {
            int r = idx >> 6, c2 = (idx & 63) * 2;
            float v0 = Cs[r * 132 + c2], v1 = Cs[r * 132 + c2 + 1];
            __nv_bfloat16 h0, l0, h1, l1;
            split1(v0, h0, l0); split1(v1, h1, l1);
            int rg = row0 + r, gc = col0 + c2;
            int b = rg >> 11, m = rg & 2047;
            __nv_bfloat16* dst = (gc < DMODEL) ? khlo : vhlo;
            int gcl = (gc < DMODEL) ? gc : gc - DMODEL;
            int h = gcl >> 6, cc = gcl & 63;
            __nv_bfloat16* o = dst + (((size_t)(b * NHEAD + h) * JDIM + m)) * 128 + cc;
            *(__nv_bfloat162*)(o)      = __halves2bfloat162(h0, h1);
            *(__nv_bfloat162*)(o + 64) = __halves2bfloat162(l0, l1);
        }
    }
}

// ---------------------------------------------------------------------------
// FA2-style flash attention (round-16, verified)
// ---------------------------------------------------------------------------
struct __align__(16) AttnW {
    __nv_bfloat16 Q2s[128][136];      // [Qh(64) | Ql(64)]  (x0.125)
    __nv_bfloat16 Khl[2][64][136];    // [Kh | Kl]
    __nv_bfloat16 Vhl[2][64][136];    // [Vh | Vl]
    __nv_bfloat16 Wh[4][64][72];      // W span ring (hi only), slot = (u>>6)&3
    __nv_bfloat16 Rx[3][128][72];     // rel scores ring, slot = (u>>6)%3
};

__device__ __forceinline__ void aw_pf_K(AttnW& S, int bb, const __nv_bfloat16* __restrict__ khl,
                                        size_t bh, int m0, int tid) {
#pragma unroll
    for (int p = 0; p < 4; ++p) {
        int i = tid + p * 256;
        int r = i >> 4, c = i & 15;
        cpasync16(&S.Khl[bb][r][c * 8], khl + (bh * JDIM + (size_t)(m0 + r)) * 128 + c * 8);
    }
}
__device__ __forceinline__ void aw_pf_V(AttnW& S, int bb, const __nv_bfloat16* __restrict__ vhl,
                                        size_t bh, int m0, int tid) {
#pragma unroll
    for (int p = 0; p < 4; ++p) {
        int i = tid + p * 256;
        int r = i >> 4, c = i & 15;
        cpasync16(&S.Vhl[bb][r][c * 8], vhl + (bh * JDIM + (size_t)(m0 + r)) * 128 + c * 8);
    }
}
__device__ __forceinline__ void aw_pf_W(AttnW& S, const __nv_bfloat16* __restrict__ rel2,
                                        int h, int ub, int tid) {
    int slot = (ub >> 6) & 3;
#pragma unroll
    for (int p = 0; p < 2; ++p) {
        int i = tid + p * 256;
        int o = i >> 3, c = i & 7;
        int u = ub + o; if (u > JDIM - 1) u = JDIM - 1;
        cpasync16(&S.Wh[slot][o][c * 8], rel2 + ((size_t)h * JDIM + u) * 64 + c * 8);
    }
}

__global__ __launch_bounds__(256, 1)
void attn_mma(const __nv_bfloat16* __restrict__ q2,
              const __nv_bfloat16* __restrict__ khl,
              const __nv_bfloat16* __restrict__ vhl,
              const __nv_bfloat16* __restrict__ rel2,
              __nv_bfloat16* __restrict__ a2) {
    extern __shared__ char smem_raw[];
    AttnW& S = *reinterpret_cast<AttnW*>(smem_raw);

    const int b  = blockIdx.z;
    const int h  = blockIdx.y;
    const int rb = (int)gridDim.x - 1 - (int)blockIdx.x;   // long blocks first
    const int r0 = rb * 128;
    const size_t bh = (size_t)(b * NHEAD + h);
    const int tid = threadIdx.x;
    const int wid = tid >> 5;
    const int lane = tid & 31;
    const int g   = lane >> 2;
    const int tig = lane & 3;
    const int rowbase = wid * 16;
    const int rl1 = rowbase + g;
    const int rl2 = rl1 + 8;

#pragma unroll
    for (int p = 0; p < 8; ++p) {
        int i = tid + p * 256;
        int r = i >> 4, c = i & 15;
        cpasync16(&S.Q2s[r][c * 8],
                  q2 + (bh * TLEN + (size_t)(r0 + r)) * 128 + c * 8);
    }
    aw_pf_K(S, 0, khl, bh, 0, tid);
    aw_pf_V(S, 0, vhl, bh, 0, tid);
    const int ubase0 = 896 - r0;
    aw_pf_W(S, rel2, h, ubase0,        tid);
    aw_pf_W(S, rel2, h, ubase0 + 64,   tid);
    aw_pf_W(S, rel2, h, ubase0 + 128,  tid);
    cp_commit();

    float accf[8][4];
#pragma unroll
    for (int i = 0; i < 8; ++i)
#pragma unroll
        for (int j = 0; j < 4; ++j) accf[i][j] = 0.f;
    float mreg[2] = {-1e30f, -1e30f};
    float lreg[2] = {0.f, 0.f};

    uint32_t aQh[4][4], aQl[4][4];

    const int ntiles = min(32, 2 * rb + 18);

    for (int mt = 0; mt < ntiles; ++mt) {
        const int cur = mt & 1;
        const int prv = cur ^ 1;
        const int m0  = mt * 64;

        cp_wait0();
        __syncthreads();

        if (mt == 0) {
            int s = lane >> 3, rr2 = lane & 7;
            int arow = rowbase + (s & 1) * 8 + rr2;
            int acol = (s >> 1) * 8;
#pragma unroll
            for (int k16 = 0; k16 < 4; ++k16) {
                ldmx4(aQh[k16], smem_u32(&S.Q2s[arow][acol + k16 * 16]));
                ldmx4(aQl[k16], smem_u32(&S.Q2s[arow][64 + acol + k16 * 16]));
            }
        }

        if (mt + 1 < ntiles) {
            aw_pf_K(S, prv, khl, bh, m0 + 64, tid);
            aw_pf_V(S, prv, vhl, bh, m0 + 64, tid);
            cp_commit();
        }

        // ---- R: compute new slot(s) = Qh @ Wh^T for warp's 16 rows ----
        {
            const int nR = (mt == 0) ? 3 : 1;
#pragma unroll
            for (int rr = 0; rr < nR; ++rr) {
                int ub = (mt == 0) ? (ubase0 + 64 * rr) : (ubase0 + 64 * (mt + 2));
                int wslot = (ub >> 6) & 3;
                int rslot = (ub >> 6) % 3;
#pragma unroll
                for (int nt = 0; nt < 8; ++nt) {
                    float c[4] = {0.f, 0.f, 0.f, 0.f};
#pragma unroll
                    for (int k16 = 0; k16 < 4; ++k16) {
                        uint32_t bw[2];
                        ldmx2(bw, smem_u32(&S.Wh[wslot][nt * 8 + (lane & 7)]
                                                 [k16 * 16 + 8 * ((lane >> 3) & 1)]));
                        mma16816(c, aQh[k16], bw);
                    }
                    int colc = 8 * nt + 2 * tig;
                    *(__nv_bfloat162*)&S.Rx[rslot][rl1][colc] =
                        __halves2bfloat162(__float2bfloat16(c[0]), __float2bfloat16(c[1]));
                    *(__nv_bfloat162*)&S.Rx[rslot][rl2][colc] =
                        __halves2bfloat162(__float2bfloat16(c[2]), __float2bfloat16(c[3]));
                }
            }
        }
        __syncwarp();

        // ---- S: 3 compensated passes into register fragments ----
        float sc[8][4];
#pragma unroll
        for (int nt = 0; nt < 8; ++nt) {
#pragma unroll
            for (int j = 0; j < 4; ++j) sc[nt][j] = 0.f;
#pragma unroll
            for (int k16 = 0; k16 < 4; ++k16) {
                uint32_t bkh[2], bkl[2];
                int krow = nt * 8 + (lane & 7);
                int kc = k16 * 16 + 8 * ((lane >> 3) & 1);
                ldmx2(bkh, smem_u32(&S.Khl[cur][krow][kc]));
                ldmx2(bkl, smem_u32(&S.Khl[cur][krow][64 + kc]));
                mma16816(sc[nt], aQh[k16], bkh);
                mma16816(sc[nt], aQl[k16], bkh);
                mma16816(sc[nt], aQh[k16], bkl);
            }
        }

        // ---- softmax in registers (rows rl1, rl2; quad reduction) ----
        uint32_t phx[2][8], plx[2][8];
        float alpha[2];
#pragma unroll
        for (int ri = 0; ri < 2; ++ri) {
            const int rl = (ri == 0) ? rl1 : rl2;
            const int mlim = r0 + rl + MEMLEN - m0;
            const int ubase = m0 + 1023 - r0 - rl;
            float sv[8][2];
            float rmax = -1e30f;
#pragma unroll
            for (int nt = 0; nt < 8; ++nt) {
#pragma unroll
                for (int j = 0; j < 2; ++j) {
                    int mm = 8 * nt + 2 * tig + j;
                    int u = ubase + mm;
                    int slot = (u >> 6) % 3;
                    float rv = __bfloat162float(S.Rx[slot][rl][u & 63]);
                    float s = sc[nt][2 * ri + j] + rv;
                    if (mm > mlim) s = -1e30f;
                    sv[nt][j] = s;
                    rmax = fmaxf(rmax, s);
                }
            }
            rmax = fmaxf(rmax, __shfl_xor_sync(0xffffffffu, rmax, 1));
            rmax = fmaxf(rmax, __shfl_xor_sync(0xffffffffu, rmax, 2));
            float mnew = fmaxf(mreg[ri], rmax);
            alpha[ri] = __expf(mreg[ri] - mnew);
            float lsum = 0.f;
#pragma unroll
            for (int nt = 0; nt < 8; ++nt) {
                float p0 = __expf(sv[nt][0] - mnew);
                float p1 = __expf(sv[nt][1] - mnew);
                lsum += p0 + p1;
                __nv_bfloat16 h0 = __float2bfloat16(p0);
                __nv_bfloat16 h1 = __float2bfloat16(p1);
                phx[ri][nt] = packbf2(h0, h1);
                plx[ri][nt] = packbf2(__float2bfloat16(p0 - __bfloat162float(h0)),
                                      __float2bfloat16(p1 - __bfloat162float(h1)));
            }
            lsum += __shfl_xor_sync(0xffffffffu, lsum, 1);
            lsum += __shfl_xor_sync(0xffffffffu, lsum, 2);
            lreg[ri] = lreg[ri] * alpha[ri] + lsum;
            mreg[ri] = mnew;
        }

        // ---- PV: rescale accf, repack P C->A fragments, mma with V ----
#pragma unroll
        for (int nt = 0; nt < 8; ++nt) {
            accf[nt][0] *= alpha[0]; accf[nt][1] *= alpha[0];
            accf[nt][2] *= alpha[1]; accf[nt][3] *= alpha[1];
        }
        uint32_t aPh[4][4], aPl[4][4];
#pragma unroll
        for (int kk = 0; kk < 4; ++kk) {
            aPh[kk][0] = phx[0][2 * kk];     aPh[kk][1] = phx[1][2 * kk];
            aPh[kk][2] = phx[0][2 * kk + 1]; aPh[kk][3] = phx[1][2 * kk + 1];
            aPl[kk][0] = plx[0][2 * kk];     aPl[kk][1] = plx[1][2 * kk];
            aPl[kk][2] = plx[0][2 * kk + 1]; aPl[kk][3] = plx[1][2 * kk + 1];
        }
        {
            int s = (lane >> 3) & 1, rr2 = lane & 7;
#pragma unroll
            for (int k16 = 0; k16 < 4; ++k16) {
                int vrow = k16 * 16 + s * 8 + rr2;
#pragma unroll
                for (int nt = 0; nt < 8; ++nt) {
                    uint32_t bhv[2], blv[2];
                    ldmx2t(bhv, smem_u32(&S.Vhl[cur][vrow][nt * 8]));
                    ldmx2t(blv, smem_u32(&S.Vhl[cur][vrow][64 + nt * 8]));
                    mma16816(accf[nt], aPh[k16], bhv);
                    mma16816(accf[nt], aPl[k16], bhv);
                    mma16816(accf[nt], aPh[k16], blv);
                }
            }
        }

        if (mt + 1 < ntiles) {
            aw_pf_W(S, rel2, h, ubase0 + 64 * (mt + 3), tid);
            cp_commit();
        }
    }

    // ---- epilogue: write a2 [row][2048] = [h | l] from fragments ----
    {
        float inv1 = 1.f / lreg[0];
        float inv2 = 1.f / lreg[1];
        size_t grow1 = (size_t)(b * TLEN + r0 + rl1) * KP2;
        size_t grow2 = (size_t)(b * TLEN + r0 + rl2) * KP2;
#pragma unroll
        for (int nt = 0; nt < 8; ++nt) {
            int col = h * 64 + 8 * nt + 2 * tig;
            float v0 = accf[nt][0] * inv1, v1 = accf[nt][1] * inv1;
            float v2 = accf[nt][2] * inv2, v3 = accf[nt][3] * inv2;
            __nv_bfloat16 h0, l0, h1, l1, h2, l2, h3, l3;
            split1(v0, h0, l0); split1(v1, h1, l1);
            split1(v2, h2, l2); split1(v3, h3, l3);
            __nv_bfloat16* o1 = a2 + grow1 + col;
            __nv_bfloat16* o2 = a2 + grow2 + col;
            *(__nv_bfloat162*)(o1)          = __halves2bfloat162(h0, h1);
            *(__nv_bfloat162*)(o1 + DMODEL) = __halves2bfloat162(l0, l1);
            *(__nv_bfloat162*)(o2)          = __halves2bfloat162(h2, h3);
            *(__nv_bfloat162*)(o2 + DMODEL) = __halves2bfloat162(l2, l3);
        }
    }
}

// ---------------------------------------------------------------------------
extern "C" void kernel_launch(void* const* d_in, const int* in_sizes, int n_in,
                              void* d_out, int out_size) {
    const float* x    = (const float*)d_in[0];
    const float* mem  = (const float*)d_in[1];
    const float* wq   = (const float*)d_in[2];
    const float* wkv  = (const float*)d_in[3];
    const float* wo   = (const float*)d_in[4];
    const float* bo   = (const float*)d_in[5];
    const float* relw = (const float*)d_in[6];

    float* out_main = (float*)d_out;
    float* mem_next = out_main + (size_t)BATCH * TLEN * DMODEL;

    __nv_bfloat16 *kvin2, *a2, *wq2, *wkv2, *wo2, *q2, *rel2, *khl, *vhl;
    cudaGetSymbolAddress((void**)&kvin2, g_kvin2);
    cudaGetSymbolAddress((void**)&a2,    g_a2);
    cudaGetSymbolAddress((void**)&wq2,   g_wq2);
    cudaGetSymbolAddress((void**)&wkv2,  g_wkv2);
    cudaGetSymbolAddress((void**)&wo2,   g_wo2);
    cudaGetSymbolAddress((void**)&q2,    g_q2);
    cudaGetSymbolAddress((void**)&rel2,  g_rel2);
    cudaGetSymbolAddress((void**)&khl,   g_khl);
    cudaGetSymbolAddress((void**)&vhl,   g_vhl);

    const int TG_SMEM = 2 * STG4 + 16 * 128 * 4;    // 90112
    const int AW_SMEM = (int)sizeof(AttnW);
    cudaFuncSetAttribute(tgemm_wmma, cudaFuncAttributeMaxDynamicSharedMemorySize, TG_SMEM);
    cudaFuncSetAttribute(attn_mma,   cudaFuncAttributeMaxDynamicSharedMemorySize, AW_SMEM);

    // operand prep (copy_x fused into kvin build; weight transposes fused)
    {
        size_t tot = (size_t)BATCH * JDIM * 256;
        build_kvin_split2<<<(unsigned)((tot + 255) / 256), 256>>>(x, mem, kvin2, mem_next);
    }
    transpose_split2_all<<<dim3(32, 32, 4), dim3(32, 8)>>>(wq, wkv, wo, wq2, wkv2, wo2);
    {
        size_t tot = (size_t)JDIM * NHEAD * 16;
        build_rel2k<<<(unsigned)((tot + 255) / 256), 256>>>(relw, rel2);
    }

    // q-proj -> q2 (mode 1); A = x rows inside kvin2 (aremap)
    tgemm_wmma<<<dim3(DMODEL / 128, BATCH * TLEN / 128), 256, TG_SMEM>>>(
        kvin2, wq2, nullptr, nullptr, q2, nullptr, nullptr, BATCH * TLEN, DMODEL, 1, 1);
    // kv-proj -> khl/vhl (mode 2)
    tgemm_wmma<<<dim3(2 * DMODEL / 128, BATCH * JDIM / 128), 256, TG_SMEM>>>(
        kvin2, wkv2, nullptr, nullptr, nullptr, khl, vhl, BATCH * JDIM, 2 * DMODEL, 2, 0);
    // flash attention -> a2 (128 q-rows per block)
    attn_mma<<<dim3(TLEN / 128, NHEAD, BATCH), 256, AW_SMEM>>>(q2, khl, vhl, rel2, a2);
    // out = attn @ wo + bo (mode 0)
    tgemm_wmma<<<dim3(DMODEL / 128, BATCH * TLEN / 128), 256, TG_SMEM>>>(
        a2, wo2, bo, out_main, nullptr, nullptr, nullptr, BATCH * TLEN, DMODEL, 0, 0);
}